// round 2
// baseline (speedup 1.0000x reference)
#include <cuda_runtime.h>

#define B_ 256
#define S_ 512
#define E_ 512
#define H_ 1024
#define HH_ 512
#define MTOK (B_ * S_)

// ---------------- scratch (device globals; no runtime allocation) ----------
__device__ float g_tmp[MTOK * HH_];   // 256 MB: relu(seq@w1x+b1x)
__device__ float g_xh[MTOK * H_];     // 512 MB: xh
__device__ float g_h[B_ * H_];        // 1 MB: recurrent state
__device__ float g_inter[B_ * HH_];   // 0.5 MB: relu(h@w1h+b1h)

// ---------------- grid barrier state ---------------------------------------
__device__ unsigned g_bar_cnt;            // zero-init at module load
__device__ volatile unsigned g_bar_gen;   // generation counter (monotonic)

__device__ __forceinline__ void grid_barrier(unsigned ncta) {
    __syncthreads();
    if (threadIdx.x == 0) {
        unsigned gen = g_bar_gen;
        __threadfence();  // make this CTA's prior global writes visible
        unsigned old = atomicAdd(&g_bar_cnt, 1u);
        if (old == ncta - 1) {
            atomicExch(&g_bar_cnt, 0u);
            __threadfence();
            g_bar_gen = gen + 1;
        } else {
            while (g_bar_gen == gen) { __nanosleep(40); }
        }
        __threadfence();  // acquire
    }
    __syncthreads();
}

__device__ __forceinline__ float fast_tanh(float x) {
    float y;
    asm("tanh.approx.f32 %0, %1;" : "=f"(y) : "f"(x));
    return y;
}

// ---------------- Phase-1 GEMM: C = act(A @ B + bias) ----------------------
// BM=128, BN=64, BK=16, TM=8, TN=4, 256 threads. M,N,K exact multiples.
__global__ __launch_bounds__(256) void ff_gemm(
    const float* __restrict__ A, const float* __restrict__ Bw,
    const float* __restrict__ bias, float* __restrict__ C,
    int K, int N, int do_relu)
{
    __shared__ float As[16][132];  // transposed A tile [BK][BM+4]
    __shared__ float Bs[16][64];

    const int tid = threadIdx.x;
    const int tx = tid & 15;   // 16 col groups (64/4)
    const int ty = tid >> 4;   // 16 row groups (128/8)
    const int rowBase = blockIdx.y * 128;
    const int colBase = blockIdx.x * 64;

    float acc[8][4];
#pragma unroll
    for (int i = 0; i < 8; i++)
#pragma unroll
        for (int j = 0; j < 4; j++) acc[i][j] = 0.f;

    for (int k0 = 0; k0 < K; k0 += 16) {
        // A tile: 128x16 = 512 float4, 2 per thread, stored transposed
#pragma unroll
        for (int j = 0; j < 2; j++) {
            int i = tid + 256 * j;
            int r = i >> 2, cc = (i & 3) * 4;
            float4 v = *(const float4*)&A[(size_t)(rowBase + r) * K + k0 + cc];
            As[cc + 0][r] = v.x; As[cc + 1][r] = v.y;
            As[cc + 2][r] = v.z; As[cc + 3][r] = v.w;
        }
        // B tile: 16x64 = 256 float4, 1 per thread
        {
            int r = tid >> 4, cc = (tid & 15) * 4;
            *(float4*)&Bs[r][cc] = *(const float4*)&Bw[(size_t)(k0 + r) * N + colBase + cc];
        }
        __syncthreads();

#pragma unroll
        for (int kk = 0; kk < 16; kk++) {
            float4 a0 = *(float4*)&As[kk][ty * 8];
            float4 a1 = *(float4*)&As[kk][ty * 8 + 4];
            float4 b  = *(float4*)&Bs[kk][tx * 4];
            float av[8] = {a0.x, a0.y, a0.z, a0.w, a1.x, a1.y, a1.z, a1.w};
#pragma unroll
            for (int i = 0; i < 8; i++) {
                acc[i][0] = fmaf(av[i], b.x, acc[i][0]);
                acc[i][1] = fmaf(av[i], b.y, acc[i][1]);
                acc[i][2] = fmaf(av[i], b.z, acc[i][2]);
                acc[i][3] = fmaf(av[i], b.w, acc[i][3]);
            }
        }
        __syncthreads();
    }

    const int c = colBase + tx * 4;
    float4 bv = *(const float4*)&bias[c];
#pragma unroll
    for (int i = 0; i < 8; i++) {
        int r = rowBase + ty * 8 + i;
        float4 v;
        v.x = acc[i][0] + bv.x; v.y = acc[i][1] + bv.y;
        v.z = acc[i][2] + bv.z; v.w = acc[i][3] + bv.w;
        if (do_relu) {
            v.x = fmaxf(v.x, 0.f); v.y = fmaxf(v.y, 0.f);
            v.z = fmaxf(v.z, 0.f); v.w = fmaxf(v.w, 0.f);
        }
        *(float4*)&C[(size_t)r * N + c] = v;
    }
}

// ---------------- Persistent recurrence kernel ------------------------------
// 128 CTAs x 256 threads (all co-resident => software grid barrier is safe).
// Per step:
//   A: inter = relu(h @ w1h + b1h)          [256,512], K=1024, 128 tiles 16x64
//   B: h = mask? tanh(xh_t + inter@w2h+b2h) [256,1024], K=512, 256 tiles (2/CTA)
#define NCTA 128

__global__ __launch_bounds__(256) void recurrence(
    const float* __restrict__ w1h, const float* __restrict__ b1h,
    const float* __restrict__ w2h, const float* __restrict__ b2h,
    const float* __restrict__ xh, const int* __restrict__ lens,
    float* __restrict__ h, float* __restrict__ inter, float* __restrict__ out)
{
    const int tid = threadIdx.x;
    const int cta = blockIdx.x;
    const int tx = tid & 15;   // 16 col groups of 4
    const int ty = tid >> 4;   // 16 rows

    __shared__ float As[16][34];
    __shared__ float Bs[32][64];

    // zero h slice (h0 = 0; must happen every replay)
    const int HSL = (B_ * H_) / NCTA;  // 2048
#pragma unroll
    for (int i = tid; i < HSL; i += 256) h[cta * HSL + i] = 0.f;
    grid_barrier(NCTA);

    const int rowA = (cta >> 3) * 16;   // 16 row blocks
    const int colA = (cta & 7) * 64;    // 8 col blocks

    for (int t = 0; t < S_; t++) {
        // ---------------- Phase A ----------------
        {
            float4 acc = make_float4(0.f, 0.f, 0.f, 0.f);
            for (int k0 = 0; k0 < H_; k0 += 32) {
                {   // A tile 16x32: float2 per thread
                    int m = tid >> 4, kk = (tid & 15) * 2;
                    float2 v = *(const float2*)&h[(rowA + m) * H_ + k0 + kk];
                    As[m][kk] = v.x; As[m][kk + 1] = v.y;
                }
#pragma unroll
                for (int j = 0; j < 2; j++) {  // B tile 32x64: 2 float4/thread
                    int i = tid + 256 * j;
                    int r = i >> 4, cc = (i & 15) * 4;
                    *(float4*)&Bs[r][cc] =
                        *(const float4*)&w1h[(k0 + r) * HH_ + colA + cc];
                }
                __syncthreads();
#pragma unroll
                for (int kk = 0; kk < 32; kk++) {
                    float a = As[ty][kk];
                    float4 b = *(float4*)&Bs[kk][tx * 4];
                    acc.x = fmaf(a, b.x, acc.x);
                    acc.y = fmaf(a, b.y, acc.y);
                    acc.z = fmaf(a, b.z, acc.z);
                    acc.w = fmaf(a, b.w, acc.w);
                }
                __syncthreads();
            }
            float4 bv = *(const float4*)&b1h[colA + tx * 4];
            float4 r;
            r.x = fmaxf(acc.x + bv.x, 0.f);
            r.y = fmaxf(acc.y + bv.y, 0.f);
            r.z = fmaxf(acc.z + bv.z, 0.f);
            r.w = fmaxf(acc.w + bv.w, 0.f);
            *(float4*)&inter[(rowA + ty) * HH_ + colA + tx * 4] = r;
        }
        grid_barrier(NCTA);

        // ---------------- Phase B (2 tiles per CTA) ----------------
#pragma unroll
        for (int s = 0; s < 2; s++) {
            int id = cta * 2 + s;
            int rowB = (id >> 4) * 16;   // 16 row blocks
            int colB = (id & 15) * 64;   // 16 col blocks
            float4 acc = make_float4(0.f, 0.f, 0.f, 0.f);
            for (int k0 = 0; k0 < HH_; k0 += 32) {
                {
                    int m = tid >> 4, kk = (tid & 15) * 2;
                    float2 v = *(const float2*)&inter[(rowB + m) * HH_ + k0 + kk];
                    As[m][kk] = v.x; As[m][kk + 1] = v.y;
                }
#pragma unroll
                for (int j = 0; j < 2; j++) {
                    int i = tid + 256 * j;
                    int r = i >> 4, cc = (i & 15) * 4;
                    *(float4*)&Bs[r][cc] =
                        *(const float4*)&w2h[(k0 + r) * H_ + colB + cc];
                }
                __syncthreads();
#pragma unroll
                for (int kk = 0; kk < 32; kk++) {
                    float a = As[ty][kk];
                    float4 b = *(float4*)&Bs[kk][tx * 4];
                    acc.x = fmaf(a, b.x, acc.x);
                    acc.y = fmaf(a, b.y, acc.y);
                    acc.z = fmaf(a, b.z, acc.z);
                    acc.w = fmaf(a, b.w, acc.w);
                }
                __syncthreads();
            }
            int r = rowB + ty;
            int c = colB + tx * 4;
            float4 bv = *(const float4*)&b2h[c];
            float4 res;
            if (t < lens[r]) {
                float4 xv = *(const float4*)&xh[((size_t)r * S_ + t) * H_ + c];
                res.x = fast_tanh(xv.x + acc.x + bv.x);
                res.y = fast_tanh(xv.y + acc.y + bv.y);
                res.z = fast_tanh(xv.z + acc.z + bv.z);
                res.w = fast_tanh(xv.w + acc.w + bv.w);
            } else {
                res = *(const float4*)&h[r * H_ + c];
            }
            *(float4*)&h[r * H_ + c] = res;
            *(float4*)&out[((size_t)r * S_ + t) * H_ + c] = res;
        }
        grid_barrier(NCTA);
    }
}

// ---------------- launcher --------------------------------------------------
extern "C" void kernel_launch(void* const* d_in, const int* in_sizes, int n_in,
                              void* d_out, int out_size) {
    const float* seq = (const float*)d_in[0];
    const int* lens  = (const int*)d_in[1];
    const float* w1x = (const float*)d_in[2];
    const float* b1x = (const float*)d_in[3];
    const float* w2x = (const float*)d_in[4];
    const float* b2x = (const float*)d_in[5];
    const float* w1h = (const float*)d_in[6];
    const float* b1h = (const float*)d_in[7];
    const float* w2h = (const float*)d_in[8];
    const float* b2h = (const float*)d_in[9];
    float* out = (float*)d_out;

    float *tmp, *xh, *h, *inter;
    cudaGetSymbolAddress((void**)&tmp, g_tmp);
    cudaGetSymbolAddress((void**)&xh, g_xh);
    cudaGetSymbolAddress((void**)&h, g_h);
    cudaGetSymbolAddress((void**)&inter, g_inter);

    // Phase 1: xh = relu(seq @ w1x + b1x) @ w2x + b2x
    ff_gemm<<<dim3(HH_ / 64, MTOK / 128), 256>>>(seq, w1x, b1x, tmp, E_, HH_, 1);
    ff_gemm<<<dim3(H_ / 64, MTOK / 128), 256>>>(tmp, w2x, b2x, xh, HH_, H_, 0);

    // Phase 2: one persistent kernel for all 512 recurrence steps
    recurrence<<<NCTA, 256>>>(w1h, b1h, w2h, b2h, xh, lens, h, inter, out);
}

// round 3
// speedup vs baseline: 1.0005x; 1.0005x over previous
#include <cuda_runtime.h>

#define B_ 256
#define S_ 512
#define E_ 512
#define H_ 1024
#define HH_ 512
#define MTOK (B_ * S_)

// ---------------- scratch (device globals; no runtime allocation) ----------
__device__ float g_tmp[MTOK * HH_];   // 256 MB: relu(seq@w1x+b1x)
__device__ float g_xh[MTOK * H_];     // 512 MB: xh
__device__ float g_h[B_ * H_];        // 1 MB: recurrent state
__device__ float g_inter[B_ * HH_];   // 0.5 MB: relu(h@w1h+b1h)

// ---------------- grid barrier state ---------------------------------------
__device__ unsigned g_bar_cnt;            // zero-init at module load
__device__ volatile unsigned g_bar_gen;   // generation counter (monotonic)

__device__ __forceinline__ void grid_barrier(unsigned ncta) {
    __syncthreads();
    if (threadIdx.x == 0) {
        unsigned gen = g_bar_gen;
        __threadfence();  // make this CTA's prior global writes visible
        unsigned old = atomicAdd(&g_bar_cnt, 1u);
        if (old == ncta - 1) {
            atomicExch(&g_bar_cnt, 0u);
            __threadfence();
            g_bar_gen = gen + 1;
        } else {
            while (g_bar_gen == gen) { __nanosleep(40); }
        }
        __threadfence();  // acquire
    }
    __syncthreads();
}

__device__ __forceinline__ float fast_tanh(float x) {
    float y;
    asm("tanh.approx.f32 %0, %1;" : "=f"(y) : "f"(x));
    return y;
}

// ---------------- Phase-1 GEMM: C = act(A @ B + bias) ----------------------
// BM=128, BN=64, BK=16, TM=8, TN=4, 256 threads. M,N,K exact multiples.
__global__ __launch_bounds__(256) void ff_gemm(
    const float* __restrict__ A, const float* __restrict__ Bw,
    const float* __restrict__ bias, float* __restrict__ C,
    int K, int N, int do_relu)
{
    __shared__ float As[16][132];  // transposed A tile [BK][BM+4]
    __shared__ float Bs[16][64];

    const int tid = threadIdx.x;
    const int tx = tid & 15;   // 16 col groups (64/4)
    const int ty = tid >> 4;   // 16 row groups (128/8)
    const int rowBase = blockIdx.y * 128;
    const int colBase = blockIdx.x * 64;

    float acc[8][4];
#pragma unroll
    for (int i = 0; i < 8; i++)
#pragma unroll
        for (int j = 0; j < 4; j++) acc[i][j] = 0.f;

    for (int k0 = 0; k0 < K; k0 += 16) {
        // A tile: 128x16 = 512 float4, 2 per thread, stored transposed
#pragma unroll
        for (int j = 0; j < 2; j++) {
            int i = tid + 256 * j;
            int r = i >> 2, cc = (i & 3) * 4;
            float4 v = *(const float4*)&A[(size_t)(rowBase + r) * K + k0 + cc];
            As[cc + 0][r] = v.x; As[cc + 1][r] = v.y;
            As[cc + 2][r] = v.z; As[cc + 3][r] = v.w;
        }
        // B tile: 16x64 = 256 float4, 1 per thread
        {
            int r = tid >> 4, cc = (tid & 15) * 4;
            *(float4*)&Bs[r][cc] = *(const float4*)&Bw[(size_t)(k0 + r) * N + colBase + cc];
        }
        __syncthreads();

#pragma unroll
        for (int kk = 0; kk < 16; kk++) {
            float4 a0 = *(float4*)&As[kk][ty * 8];
            float4 a1 = *(float4*)&As[kk][ty * 8 + 4];
            float4 b  = *(float4*)&Bs[kk][tx * 4];
            float av[8] = {a0.x, a0.y, a0.z, a0.w, a1.x, a1.y, a1.z, a1.w};
#pragma unroll
            for (int i = 0; i < 8; i++) {
                acc[i][0] = fmaf(av[i], b.x, acc[i][0]);
                acc[i][1] = fmaf(av[i], b.y, acc[i][1]);
                acc[i][2] = fmaf(av[i], b.z, acc[i][2]);
                acc[i][3] = fmaf(av[i], b.w, acc[i][3]);
            }
        }
        __syncthreads();
    }

    const int c = colBase + tx * 4;
    float4 bv = *(const float4*)&bias[c];
#pragma unroll
    for (int i = 0; i < 8; i++) {
        int r = rowBase + ty * 8 + i;
        float4 v;
        v.x = acc[i][0] + bv.x; v.y = acc[i][1] + bv.y;
        v.z = acc[i][2] + bv.z; v.w = acc[i][3] + bv.w;
        if (do_relu) {
            v.x = fmaxf(v.x, 0.f); v.y = fmaxf(v.y, 0.f);
            v.z = fmaxf(v.z, 0.f); v.w = fmaxf(v.w, 0.f);
        }
        *(float4*)&C[(size_t)r * N + c] = v;
    }
}

// ---------------- Persistent recurrence kernel ------------------------------
// 128 CTAs x 256 threads (all co-resident => software grid barrier is safe).
// Per step:
//   A: inter = relu(h @ w1h + b1h)          [256,512], K=1024, 128 tiles 16x64
//   B: h = mask? tanh(xh_t + inter@w2h+b2h) [256,1024], K=512, 256 tiles (2/CTA)
#define NCTA 128

__global__ __launch_bounds__(256) void recurrence(
    const float* __restrict__ w1h, const float* __restrict__ b1h,
    const float* __restrict__ w2h, const float* __restrict__ b2h,
    const float* __restrict__ xh, const int* __restrict__ lens,
    float* __restrict__ h, float* __restrict__ inter, float* __restrict__ out)
{
    const int tid = threadIdx.x;
    const int cta = blockIdx.x;
    const int tx = tid & 15;   // 16 col groups of 4
    const int ty = tid >> 4;   // 16 rows

    __shared__ float As[16][34];
    __shared__ float Bs[32][64];

    // zero h slice (h0 = 0; must happen every replay)
    const int HSL = (B_ * H_) / NCTA;  // 2048
#pragma unroll
    for (int i = tid; i < HSL; i += 256) h[cta * HSL + i] = 0.f;
    grid_barrier(NCTA);

    const int rowA = (cta >> 3) * 16;   // 16 row blocks
    const int colA = (cta & 7) * 64;    // 8 col blocks

    for (int t = 0; t < S_; t++) {
        // ---------------- Phase A ----------------
        {
            float4 acc = make_float4(0.f, 0.f, 0.f, 0.f);
            for (int k0 = 0; k0 < H_; k0 += 32) {
                {   // A tile 16x32: float2 per thread
                    int m = tid >> 4, kk = (tid & 15) * 2;
                    float2 v = *(const float2*)&h[(rowA + m) * H_ + k0 + kk];
                    As[m][kk] = v.x; As[m][kk + 1] = v.y;
                }
#pragma unroll
                for (int j = 0; j < 2; j++) {  // B tile 32x64: 2 float4/thread
                    int i = tid + 256 * j;
                    int r = i >> 4, cc = (i & 15) * 4;
                    *(float4*)&Bs[r][cc] =
                        *(const float4*)&w1h[(k0 + r) * HH_ + colA + cc];
                }
                __syncthreads();
#pragma unroll
                for (int kk = 0; kk < 32; kk++) {
                    float a = As[ty][kk];
                    float4 b = *(float4*)&Bs[kk][tx * 4];
                    acc.x = fmaf(a, b.x, acc.x);
                    acc.y = fmaf(a, b.y, acc.y);
                    acc.z = fmaf(a, b.z, acc.z);
                    acc.w = fmaf(a, b.w, acc.w);
                }
                __syncthreads();
            }
            float4 bv = *(const float4*)&b1h[colA + tx * 4];
            float4 r;
            r.x = fmaxf(acc.x + bv.x, 0.f);
            r.y = fmaxf(acc.y + bv.y, 0.f);
            r.z = fmaxf(acc.z + bv.z, 0.f);
            r.w = fmaxf(acc.w + bv.w, 0.f);
            *(float4*)&inter[(rowA + ty) * HH_ + colA + tx * 4] = r;
        }
        grid_barrier(NCTA);

        // ---------------- Phase B (2 tiles per CTA) ----------------
#pragma unroll
        for (int s = 0; s < 2; s++) {
            int id = cta * 2 + s;
            int rowB = (id >> 4) * 16;   // 16 row blocks
            int colB = (id & 15) * 64;   // 16 col blocks
            float4 acc = make_float4(0.f, 0.f, 0.f, 0.f);
            for (int k0 = 0; k0 < HH_; k0 += 32) {
                {
                    int m = tid >> 4, kk = (tid & 15) * 2;
                    float2 v = *(const float2*)&inter[(rowB + m) * HH_ + k0 + kk];
                    As[m][kk] = v.x; As[m][kk + 1] = v.y;
                }
#pragma unroll
                for (int j = 0; j < 2; j++) {
                    int i = tid + 256 * j;
                    int r = i >> 4, cc = (i & 15) * 4;
                    *(float4*)&Bs[r][cc] =
                        *(const float4*)&w2h[(k0 + r) * H_ + colB + cc];
                }
                __syncthreads();
#pragma unroll
                for (int kk = 0; kk < 32; kk++) {
                    float a = As[ty][kk];
                    float4 b = *(float4*)&Bs[kk][tx * 4];
                    acc.x = fmaf(a, b.x, acc.x);
                    acc.y = fmaf(a, b.y, acc.y);
                    acc.z = fmaf(a, b.z, acc.z);
                    acc.w = fmaf(a, b.w, acc.w);
                }
                __syncthreads();
            }
            int r = rowB + ty;
            int c = colB + tx * 4;
            float4 bv = *(const float4*)&b2h[c];
            float4 res;
            if (t < lens[r]) {
                float4 xv = *(const float4*)&xh[((size_t)r * S_ + t) * H_ + c];
                res.x = fast_tanh(xv.x + acc.x + bv.x);
                res.y = fast_tanh(xv.y + acc.y + bv.y);
                res.z = fast_tanh(xv.z + acc.z + bv.z);
                res.w = fast_tanh(xv.w + acc.w + bv.w);
            } else {
                res = *(const float4*)&h[r * H_ + c];
            }
            *(float4*)&h[r * H_ + c] = res;
            *(float4*)&out[((size_t)r * S_ + t) * H_ + c] = res;
        }
        grid_barrier(NCTA);
    }
}

// ---------------- launcher --------------------------------------------------
extern "C" void kernel_launch(void* const* d_in, const int* in_sizes, int n_in,
                              void* d_out, int out_size) {
    const float* seq = (const float*)d_in[0];
    const int* lens  = (const int*)d_in[1];
    const float* w1x = (const float*)d_in[2];
    const float* b1x = (const float*)d_in[3];
    const float* w2x = (const float*)d_in[4];
    const float* b2x = (const float*)d_in[5];
    const float* w1h = (const float*)d_in[6];
    const float* b1h = (const float*)d_in[7];
    const float* w2h = (const float*)d_in[8];
    const float* b2h = (const float*)d_in[9];
    float* out = (float*)d_out;

    float *tmp, *xh, *h, *inter;
    cudaGetSymbolAddress((void**)&tmp, g_tmp);
    cudaGetSymbolAddress((void**)&xh, g_xh);
    cudaGetSymbolAddress((void**)&h, g_h);
    cudaGetSymbolAddress((void**)&inter, g_inter);

    // Phase 1: xh = relu(seq @ w1x + b1x) @ w2x + b2x
    ff_gemm<<<dim3(HH_ / 64, MTOK / 128), 256>>>(seq, w1x, b1x, tmp, E_, HH_, 1);
    ff_gemm<<<dim3(H_ / 64, MTOK / 128), 256>>>(tmp, w2x, b2x, xh, HH_, H_, 0);

    // Phase 2: one persistent kernel for all 512 recurrence steps
    recurrence<<<NCTA, 256>>>(w1h, b1h, w2h, b2h, xh, lens, h, inter, out);
}

// round 5
// speedup vs baseline: 2.1511x; 2.1499x over previous
#include <cuda_runtime.h>
#include <cuda_bf16.h>
#include <cstdint>

#define B_ 256
#define S_ 512
#define E_ 512
#define H_ 1024
#define HH_ 512
#define MTOK (B_ * S_)

typedef __nv_bfloat16 bf16;

// ---------------- device-global scratch ------------------------------------
__device__ bf16 g_seqh[(size_t)MTOK * E_];
__device__ bf16 g_seql[(size_t)MTOK * E_];
__device__ bf16 g_tmph[(size_t)MTOK * HH_];
__device__ bf16 g_tmpl[(size_t)MTOK * HH_];
__device__ float g_xh[(size_t)MTOK * H_];
__device__ bf16 g_w1xTh[HH_ * E_], g_w1xTl[HH_ * E_];   // [N,K]
__device__ bf16 g_w2xTh[H_ * HH_], g_w2xTl[H_ * HH_];
__device__ bf16 g_w1hTh[HH_ * H_], g_w1hTl[HH_ * H_];
__device__ bf16 g_w2hTh[H_ * HH_], g_w2hTl[H_ * HH_];
__device__ float g_h[B_ * H_];
__device__ bf16 g_hh[B_ * H_], g_hl[B_ * H_];
__device__ bf16 g_ih[B_ * HH_], g_il[B_ * HH_];
__device__ unsigned g_bar_cnt;
__device__ volatile unsigned g_bar_gen;

// ---------------- helpers ----------------------------------------------------
__device__ __forceinline__ float fast_tanh(float x) {
    float y; asm("tanh.approx.f32 %0, %1;" : "=f"(y) : "f"(x)); return y;
}
__device__ __forceinline__ void hmma(float c[4], const uint32_t a[4], const uint32_t b[2]) {
    asm volatile("mma.sync.aligned.m16n8k16.row.col.f32.bf16.bf16.f32 "
        "{%0,%1,%2,%3}, {%4,%5,%6,%7}, {%8,%9}, {%0,%1,%2,%3};"
        : "+f"(c[0]), "+f"(c[1]), "+f"(c[2]), "+f"(c[3])
        : "r"(a[0]), "r"(a[1]), "r"(a[2]), "r"(a[3]), "r"(b[0]), "r"(b[1]));
}
// A frag (m16 x k16, row-major source tile with row stride `str` bf16)
__device__ __forceinline__ void lda_frag(uint32_t a[4], const bf16* p, int str, int lane) {
    const bf16* q = p + (lane >> 2) * str + (lane & 3) * 2;
    a[0] = *(const uint32_t*)q;
    a[1] = *(const uint32_t*)(q + 8 * str);
    a[2] = *(const uint32_t*)(q + 8);
    a[3] = *(const uint32_t*)(q + 8 * str + 8);
}
// B frag (k16 x n8) from W^T tile stored [n][k] row-major
__device__ __forceinline__ void ldb_frag(uint32_t b[2], const bf16* p, int str, int lane) {
    const bf16* q = p + (lane >> 2) * str + (lane & 3) * 2;
    b[0] = *(const uint32_t*)q;
    b[1] = *(const uint32_t*)(q + 8);
}
// Load [ROWS x KCH] bf16 tile (row-major, leading dim ld) into smem, stride KCH+8.
template <int ROWS, int KCH>
__device__ __forceinline__ void ld_tile(bf16* dst, const bf16* __restrict__ src,
                                        size_t row0, int ld, int k0, int tid) {
    constexpr int STR = KCH + 8;
    constexpr int NV = ROWS * KCH / 8;
#pragma unroll
    for (int i = tid; i < NV; i += 256) {
        int r = i / (KCH / 8), c = i % (KCH / 8);
        *(uint4*)(dst + r * STR + c * 8) =
            *(const uint4*)(src + (row0 + (size_t)r) * (size_t)ld + k0 + c * 8);
    }
}

__device__ __forceinline__ void grid_barrier(unsigned ncta) {
    __syncthreads();
    if (threadIdx.x == 0) {
        unsigned gen = g_bar_gen;
        __threadfence();
        unsigned old = atomicAdd(&g_bar_cnt, 1u);
        if (old == ncta - 1) {
            atomicExch(&g_bar_cnt, 0u);
            __threadfence();
            g_bar_gen = gen + 1;
        } else {
            while (g_bar_gen == gen) { __nanosleep(40); }
        }
        __threadfence();
    }
    __syncthreads();
}

// ---------------- prep kernels ----------------------------------------------
__global__ void split_kernel(const float* __restrict__ x, bf16* __restrict__ h,
                             bf16* __restrict__ l, size_t n) {
    size_t i = (size_t)blockIdx.x * 256 + threadIdx.x;
    if (i < n) {
        float v = x[i];
        bf16 a = __float2bfloat16(v);
        h[i] = a;
        l[i] = __float2bfloat16(v - __bfloat162float(a));
    }
}
__global__ void transpose_split(const float* __restrict__ W, bf16* __restrict__ Th,
                                bf16* __restrict__ Tl, int K, int N) {
    int idx = blockIdx.x * 256 + threadIdx.x;
    if (idx < N * K) {
        int n = idx / K, k = idx % K;
        float v = W[k * N + n];
        bf16 a = __float2bfloat16(v);
        Th[idx] = a;
        Tl[idx] = __float2bfloat16(v - __bfloat162float(a));
    }
}

// ---------------- phase-1 GEMM: out = act(A @ W^T + bias) -------------------
// Tile 128x128, K chunk 64. 8 warps: wm=wid&3 (32 rows), wn=wid>>2 (64 cols).
#define P1_STR 72
#define P1_SA_H 0
#define P1_SA_L (128 * P1_STR)
#define P1_SB_H (2 * 128 * P1_STR)
#define P1_SB_L (3 * 128 * P1_STR)
#define P1_SMEM (4 * 128 * P1_STR * 2)

__global__ __launch_bounds__(256) void ff_mma(
    const bf16* __restrict__ Ah, const bf16* __restrict__ Al,
    const bf16* __restrict__ Bh, const bf16* __restrict__ Bl,
    const float* __restrict__ bias, float* __restrict__ outF,
    bf16* __restrict__ outH, bf16* __restrict__ outL,
    int K, int N, int relu_split)
{
    extern __shared__ bf16 sm[];
    const int tid = threadIdx.x, lane = tid & 31, wid = tid >> 5;
    const int wm = wid & 3, wn = wid >> 2;
    const size_t rowBase = (size_t)blockIdx.y * 128;
    const int colBase = blockIdx.x * 128;

    float acc[2][8][4];
#pragma unroll
    for (int i = 0; i < 2; i++)
#pragma unroll
        for (int j = 0; j < 8; j++)
#pragma unroll
            for (int q = 0; q < 4; q++) acc[i][j][q] = 0.f;

    for (int kc = 0; kc < K; kc += 64) {
        ld_tile<128, 64>(sm + P1_SA_H, Ah, rowBase, K, kc, tid);
        ld_tile<128, 64>(sm + P1_SA_L, Al, rowBase, K, kc, tid);
        ld_tile<128, 64>(sm + P1_SB_H, Bh, (size_t)colBase, K, kc, tid);
        ld_tile<128, 64>(sm + P1_SB_L, Bl, (size_t)colBase, K, kc, tid);
        __syncthreads();
#pragma unroll
        for (int ks = 0; ks < 4; ks++) {
            int ko = ks * 16;
            uint32_t ah[2][4], al[2][4];
#pragma unroll
            for (int mf = 0; mf < 2; mf++) {
                lda_frag(ah[mf], sm + P1_SA_H + (wm * 32 + mf * 16) * P1_STR + ko, P1_STR, lane);
                lda_frag(al[mf], sm + P1_SA_L + (wm * 32 + mf * 16) * P1_STR + ko, P1_STR, lane);
            }
#pragma unroll
            for (int nf = 0; nf < 8; nf++) {
                uint32_t bh[2], bl[2];
                ldb_frag(bh, sm + P1_SB_H + (wn * 64 + nf * 8) * P1_STR + ko, P1_STR, lane);
                ldb_frag(bl, sm + P1_SB_L + (wn * 64 + nf * 8) * P1_STR + ko, P1_STR, lane);
#pragma unroll
                for (int mf = 0; mf < 2; mf++) {
                    hmma(acc[mf][nf], ah[mf], bh);
                    hmma(acc[mf][nf], ah[mf], bl);
                    hmma(acc[mf][nf], al[mf], bh);
                }
            }
        }
        __syncthreads();
    }

    // epilogue
#pragma unroll
    for (int mf = 0; mf < 2; mf++) {
#pragma unroll
        for (int nf = 0; nf < 8; nf++) {
            int cg = colBase + wn * 64 + nf * 8 + (lane & 3) * 2;
            float b0 = bias[cg], b1 = bias[cg + 1];
#pragma unroll
            for (int half = 0; half < 2; half++) {
                size_t rg = rowBase + wm * 32 + mf * 16 + (lane >> 2) + half * 8;
                float v0 = acc[mf][nf][half * 2] + b0;
                float v1 = acc[mf][nf][half * 2 + 1] + b1;
                if (relu_split) {
                    v0 = fmaxf(v0, 0.f);
                    v1 = fmaxf(v1, 0.f);
                    __nv_bfloat162 hv, lv;
                    hv.x = __float2bfloat16(v0);
                    hv.y = __float2bfloat16(v1);
                    lv.x = __float2bfloat16(v0 - __bfloat162float(hv.x));
                    lv.y = __float2bfloat16(v1 - __bfloat162float(hv.y));
                    *(__nv_bfloat162*)&outH[rg * N + cg] = hv;
                    *(__nv_bfloat162*)&outL[rg * N + cg] = lv;
                } else {
                    float2 fv = make_float2(v0, v1);
                    *(float2*)&outF[rg * N + cg] = fv;
                }
            }
        }
    }
}

// ---------------- persistent recurrence (128 CTAs) ---------------------------
// Phase A: inter = relu(h @ w1h + b1h): tiles 32x32, K=1024 (8 chunks of 128)
// Phase B: h' = mask ? tanh(xh_t + inter @ w2h + b2h) : h: tiles 32x64, K=512
#define RN 128
#define R_STR 136
#define R_SA_H 0
#define R_SA_L (32 * R_STR)
#define R_SB_H (2 * 32 * R_STR)
#define R_SB_L (R_SB_H + 64 * R_STR)
#define R_SMEM ((R_SB_H + 2 * 64 * R_STR) * 2)   // bytes

__global__ __launch_bounds__(256) void recurrence(
    const float* __restrict__ b1h, const float* __restrict__ b2h,
    const int* __restrict__ lens, float* __restrict__ out)
{
    extern __shared__ bf16 sm[];
    float* red = (float*)sm;  // aliases chunk buffers (used only between syncs)
    const int tid = threadIdx.x, lane = tid & 31, wid = tid >> 5;
    const int wm = wid & 1, wk = wid >> 1;
    const int cta = blockIdx.x;
    const size_t rbase = (size_t)(cta >> 4) * 32;
    const int cbaseA = (cta & 15) * 32;
    const int cbaseB = (cta & 15) * 64;

    // reset h state (graph replays)
    const int HSL = (B_ * H_) / RN;
    for (int i = tid; i < HSL; i += 256) {
        int j = cta * HSL + i;
        g_h[j] = 0.f;
        g_hh[j] = __float2bfloat16(0.f);
        g_hl[j] = __float2bfloat16(0.f);
    }
    grid_barrier(RN);

    for (int t = 0; t < S_; t++) {
        // ================= phase A =================
        {
            float acc[4][4];
#pragma unroll
            for (int i = 0; i < 4; i++)
#pragma unroll
                for (int j = 0; j < 4; j++) acc[i][j] = 0.f;

            for (int kc = 0; kc < 8; kc++) {
                int k0 = kc * 128;
                ld_tile<32, 128>(sm + R_SA_H, g_hh, rbase, H_, k0, tid);
                ld_tile<32, 128>(sm + R_SA_L, g_hl, rbase, H_, k0, tid);
                ld_tile<32, 128>(sm + R_SB_H, g_w1hTh, (size_t)cbaseA, H_, k0, tid);
                ld_tile<32, 128>(sm + R_SB_L, g_w1hTl, (size_t)cbaseA, H_, k0, tid);
                __syncthreads();
#pragma unroll
                for (int ks = 0; ks < 2; ks++) {
                    int ko = wk * 32 + ks * 16;
                    uint32_t ah[4], al[4];
                    lda_frag(ah, sm + R_SA_H + wm * 16 * R_STR + ko, R_STR, lane);
                    lda_frag(al, sm + R_SA_L + wm * 16 * R_STR + ko, R_STR, lane);
#pragma unroll
                    for (int nf = 0; nf < 4; nf++) {
                        uint32_t bh[2], bl[2];
                        ldb_frag(bh, sm + R_SB_H + nf * 8 * R_STR + ko, R_STR, lane);
                        ldb_frag(bl, sm + R_SB_L + nf * 8 * R_STR + ko, R_STR, lane);
                        hmma(acc[nf], ah, bh);
                        hmma(acc[nf], ah, bl);
                        hmma(acc[nf], al, bh);
                    }
                }
                __syncthreads();
            }
            // k-reduction across 4 wk warps
#pragma unroll
            for (int nf = 0; nf < 4; nf++) {
                int base = wid * 512 + (lane >> 2) * 32 + nf * 8 + (lane & 3) * 2;
                red[base] = acc[nf][0];
                red[base + 1] = acc[nf][1];
                red[base + 256] = acc[nf][2];
                red[base + 257] = acc[nf][3];
            }
            __syncthreads();
            int r_loc = tid >> 3, c4 = (tid & 7) * 4;
            int wmv = r_loc >> 4, rr = r_loc & 15;
            float4 s = make_float4(0.f, 0.f, 0.f, 0.f);
#pragma unroll
            for (int w = 0; w < 4; w++) {
                const float* p = red + (w * 2 + wmv) * 512 + rr * 32 + c4;
                s.x += p[0]; s.y += p[1]; s.z += p[2]; s.w += p[3];
            }
            size_t rg = rbase + r_loc;
            int cg = cbaseA + c4;
            float4 bv = *(const float4*)&b1h[cg];
            float x0 = fmaxf(s.x + bv.x, 0.f), x1 = fmaxf(s.y + bv.y, 0.f);
            float x2 = fmaxf(s.z + bv.z, 0.f), x3 = fmaxf(s.w + bv.w, 0.f);
            __nv_bfloat162 hv0, lv0, hv1, lv1;
            hv0.x = __float2bfloat16(x0); hv0.y = __float2bfloat16(x1);
            lv0.x = __float2bfloat16(x0 - __bfloat162float(hv0.x));
            lv0.y = __float2bfloat16(x1 - __bfloat162float(hv0.y));
            hv1.x = __float2bfloat16(x2); hv1.y = __float2bfloat16(x3);
            lv1.x = __float2bfloat16(x2 - __bfloat162float(hv1.x));
            lv1.y = __float2bfloat16(x3 - __bfloat162float(hv1.y));
            *(__nv_bfloat162*)&g_ih[rg * HH_ + cg] = hv0;
            *(__nv_bfloat162*)&g_ih[rg * HH_ + cg + 2] = hv1;
            *(__nv_bfloat162*)&g_il[rg * HH_ + cg] = lv0;
            *(__nv_bfloat162*)&g_il[rg * HH_ + cg + 2] = lv1;
        }
        grid_barrier(RN);

        // ================= phase B =================
        {
            float acc[8][4];
#pragma unroll
            for (int i = 0; i < 8; i++)
#pragma unroll
                for (int j = 0; j < 4; j++) acc[i][j] = 0.f;

            for (int kc = 0; kc < 4; kc++) {
                int k0 = kc * 128;
                ld_tile<32, 128>(sm + R_SA_H, g_ih, rbase, HH_, k0, tid);
                ld_tile<32, 128>(sm + R_SA_L, g_il, rbase, HH_, k0, tid);
                ld_tile<64, 128>(sm + R_SB_H, g_w2hTh, (size_t)cbaseB, HH_, k0, tid);
                ld_tile<64, 128>(sm + R_SB_L, g_w2hTl, (size_t)cbaseB, HH_, k0, tid);
                __syncthreads();
#pragma unroll
                for (int ks = 0; ks < 2; ks++) {
                    int ko = wk * 32 + ks * 16;
                    uint32_t ah[4], al[4];
                    lda_frag(ah, sm + R_SA_H + wm * 16 * R_STR + ko, R_STR, lane);
                    lda_frag(al, sm + R_SA_L + wm * 16 * R_STR + ko, R_STR, lane);
#pragma unroll
                    for (int nf = 0; nf < 8; nf++) {
                        uint32_t bh[2], bl[2];
                        ldb_frag(bh, sm + R_SB_H + nf * 8 * R_STR + ko, R_STR, lane);
                        ldb_frag(bl, sm + R_SB_L + nf * 8 * R_STR + ko, R_STR, lane);
                        hmma(acc[nf], ah, bh);
                        hmma(acc[nf], ah, bl);
                        hmma(acc[nf], al, bh);
                    }
                }
                __syncthreads();
            }
#pragma unroll
            for (int nf = 0; nf < 8; nf++) {
                int base = wid * 1024 + (lane >> 2) * 64 + nf * 8 + (lane & 3) * 2;
                red[base] = acc[nf][0];
                red[base + 1] = acc[nf][1];
                red[base + 512] = acc[nf][2];
                red[base + 513] = acc[nf][3];
            }
            __syncthreads();
            int r_loc = tid >> 3, c8 = (tid & 7) * 8;
            int wmv = r_loc >> 4, rr = r_loc & 15;
            size_t rg = rbase + r_loc;
            const bool on = (t < lens[rg]);
#pragma unroll
            for (int j = 0; j < 2; j++) {
                int cg = cbaseB + c8 + j * 4;
                float4 s = make_float4(0.f, 0.f, 0.f, 0.f);
#pragma unroll
                for (int w = 0; w < 4; w++) {
                    const float* p = red + (w * 2 + wmv) * 1024 + rr * 64 + c8 + j * 4;
                    s.x += p[0]; s.y += p[1]; s.z += p[2]; s.w += p[3];
                }
                float4 res;
                if (on) {
                    float4 xv = *(const float4*)&g_xh[(rg * S_ + t) * H_ + cg];
                    float4 bv = *(const float4*)&b2h[cg];
                    res.x = fast_tanh(xv.x + s.x + bv.x);
                    res.y = fast_tanh(xv.y + s.y + bv.y);
                    res.z = fast_tanh(xv.z + s.z + bv.z);
                    res.w = fast_tanh(xv.w + s.w + bv.w);
                } else {
                    res = *(const float4*)&g_h[rg * H_ + cg];
                }
                *(float4*)&g_h[rg * H_ + cg] = res;
                *(float4*)&out[(rg * S_ + t) * H_ + cg] = res;
                __nv_bfloat162 h0, l0, h1, l1;
                h0.x = __float2bfloat16(res.x); h0.y = __float2bfloat16(res.y);
                l0.x = __float2bfloat16(res.x - __bfloat162float(h0.x));
                l0.y = __float2bfloat16(res.y - __bfloat162float(h0.y));
                h1.x = __float2bfloat16(res.z); h1.y = __float2bfloat16(res.w);
                l1.x = __float2bfloat16(res.z - __bfloat162float(h1.x));
                l1.y = __float2bfloat16(res.w - __bfloat162float(h1.y));
                *(__nv_bfloat162*)&g_hh[rg * H_ + cg] = h0;
                *(__nv_bfloat162*)&g_hh[rg * H_ + cg + 2] = h1;
                *(__nv_bfloat162*)&g_hl[rg * H_ + cg] = l0;
                *(__nv_bfloat162*)&g_hl[rg * H_ + cg + 2] = l1;
            }
        }
        grid_barrier(RN);
    }
}

// ---------------- launcher --------------------------------------------------
extern "C" void kernel_launch(void* const* d_in, const int* in_sizes, int n_in,
                              void* d_out, int out_size) {
    const float* seq = (const float*)d_in[0];
    const int* lens  = (const int*)d_in[1];
    const float* w1x = (const float*)d_in[2];
    const float* b1x = (const float*)d_in[3];
    const float* w2x = (const float*)d_in[4];
    const float* b2x = (const float*)d_in[5];
    const float* w1h = (const float*)d_in[6];
    const float* b1h = (const float*)d_in[7];
    const float* w2h = (const float*)d_in[8];
    const float* b2h = (const float*)d_in[9];
    float* out = (float*)d_out;

    bf16 *seqh, *seql, *tmph, *tmpl;
    bf16 *w1xh, *w1xl, *w2xh, *w2xl, *w1hh, *w1hl, *w2hh, *w2hl;
    float* xh;
    cudaGetSymbolAddress((void**)&seqh, g_seqh);
    cudaGetSymbolAddress((void**)&seql, g_seql);
    cudaGetSymbolAddress((void**)&tmph, g_tmph);
    cudaGetSymbolAddress((void**)&tmpl, g_tmpl);
    cudaGetSymbolAddress((void**)&xh, g_xh);
    cudaGetSymbolAddress((void**)&w1xh, g_w1xTh);
    cudaGetSymbolAddress((void**)&w1xl, g_w1xTl);
    cudaGetSymbolAddress((void**)&w2xh, g_w2xTh);
    cudaGetSymbolAddress((void**)&w2xl, g_w2xTl);
    cudaGetSymbolAddress((void**)&w1hh, g_w1hTh);
    cudaGetSymbolAddress((void**)&w1hl, g_w1hTl);
    cudaGetSymbolAddress((void**)&w2hh, g_w2hTh);
    cudaGetSymbolAddress((void**)&w2hl, g_w2hTl);

    cudaFuncSetAttribute(ff_mma, cudaFuncAttributeMaxDynamicSharedMemorySize, P1_SMEM);
    cudaFuncSetAttribute(recurrence, cudaFuncAttributeMaxDynamicSharedMemorySize, R_SMEM);

    size_t nseq = (size_t)MTOK * E_;
    split_kernel<<<(unsigned)((nseq + 255) / 256), 256>>>(seq, seqh, seql, nseq);
    transpose_split<<<(E_ * HH_ + 255) / 256, 256>>>(w1x, w1xh, w1xl, E_, HH_);
    transpose_split<<<(HH_ * H_ + 255) / 256, 256>>>(w2x, w2xh, w2xl, HH_, H_);
    transpose_split<<<(H_ * HH_ + 255) / 256, 256>>>(w1h, w1hh, w1hl, H_, HH_);
    transpose_split<<<(HH_ * H_ + 255) / 256, 256>>>(w2h, w2hh, w2hl, HH_, H_);

    // phase 1
    ff_mma<<<dim3(HH_ / 128, MTOK / 128), 256, P1_SMEM>>>(
        seqh, seql, w1xh, w1xl, b1x, nullptr, tmph, tmpl, E_, HH_, 1);
    ff_mma<<<dim3(H_ / 128, MTOK / 128), 256, P1_SMEM>>>(
        tmph, tmpl, w2xh, w2xl, b2x, xh, nullptr, nullptr, HH_, H_, 0);

    // phase 2
    recurrence<<<RN, 256, R_SMEM>>>(b1h, b2h, lens, out);
}

// round 6
// speedup vs baseline: 2.8238x; 1.3128x over previous
#include <cuda_runtime.h>
#include <cuda_bf16.h>
#include <cstdint>

#define B_ 256
#define S_ 512
#define E_ 512
#define H_ 1024
#define HH_ 512
#define MTOK (B_ * S_)

typedef __nv_bfloat16 bf16;

// ---------------- device-global scratch ------------------------------------
__device__ bf16 g_seqh[(size_t)MTOK * E_];
__device__ bf16 g_seql[(size_t)MTOK * E_];
__device__ bf16 g_tmph[(size_t)MTOK * HH_];
__device__ bf16 g_tmpl[(size_t)MTOK * HH_];
__device__ float g_xh[(size_t)MTOK * H_];
__device__ bf16 g_w1xTh[HH_ * E_], g_w1xTl[HH_ * E_];   // [N,K]
__device__ bf16 g_w2xTh[H_ * HH_], g_w2xTl[H_ * HH_];
__device__ bf16 g_w1hTh[HH_ * H_], g_w1hTl[HH_ * H_];
__device__ bf16 g_w2hTh[H_ * HH_], g_w2hTl[H_ * HH_];
__device__ float g_h[B_ * H_];
__device__ bf16 g_hh[B_ * H_], g_hl[B_ * H_];
__device__ bf16 g_ih[B_ * HH_], g_il[B_ * HH_];
// group-local barrier state (8 groups, 128B stride)
__device__ unsigned g_gcnt[8 * 32];
__device__ volatile unsigned g_ggen[8 * 32];

// ---------------- helpers ----------------------------------------------------
__device__ __forceinline__ uint32_t smem_u32(const void* p) {
    uint32_t r;
    asm("{ .reg .u64 t; cvta.to.shared.u64 t, %1; cvt.u32.u64 %0, t; }" : "=r"(r) : "l"(p));
    return r;
}
__device__ __forceinline__ float fast_tanh(float x) {
    float y; asm("tanh.approx.f32 %0, %1;" : "=f"(y) : "f"(x)); return y;
}
__device__ __forceinline__ void hmma(float c[4], const uint32_t a[4], const uint32_t b[2]) {
    asm volatile("mma.sync.aligned.m16n8k16.row.col.f32.bf16.bf16.f32 "
        "{%0,%1,%2,%3}, {%4,%5,%6,%7}, {%8,%9}, {%0,%1,%2,%3};"
        : "+f"(c[0]), "+f"(c[1]), "+f"(c[2]), "+f"(c[3])
        : "r"(a[0]), "r"(a[1]), "r"(a[2]), "r"(a[3]), "r"(b[0]), "r"(b[1]));
}
// ldmatrix x4: A frag m16k16 from row-major smem tile (stride str bf16)
__device__ __forceinline__ void ldsm4(uint32_t a[4], const bf16* p, int str, int lane) {
    uint32_t addr = smem_u32(p + (lane & 15) * str + (lane >> 4) * 8);
    asm volatile("ldmatrix.sync.aligned.m8n8.x4.shared.b16 {%0,%1,%2,%3}, [%4];"
        : "=r"(a[0]), "=r"(a[1]), "=r"(a[2]), "=r"(a[3]) : "r"(addr));
}
// ldmatrix x2: B frag k16n8 from W^T [n][k] row-major smem tile
__device__ __forceinline__ void ldsm2(uint32_t b[2], const bf16* p, int str, int lane) {
    uint32_t addr = smem_u32(p + (lane & 7) * str + ((lane >> 3) & 1) * 8);
    asm volatile("ldmatrix.sync.aligned.m8n8.x2.shared.b16 {%0,%1}, [%2];"
        : "=r"(b[0]), "=r"(b[1]) : "r"(addr));
}
__device__ __forceinline__ void cp16(bf16* s, const bf16* g) {
    uint32_t sa = smem_u32(s);
    asm volatile("cp.async.cg.shared.global [%0], [%1], 16;" :: "r"(sa), "l"(g));
}
#define CP_COMMIT() asm volatile("cp.async.commit_group;" ::: "memory")
#define CP_WAIT(n) asm volatile("cp.async.wait_group %0;" :: "n"(n) : "memory")

// async-load [ROWS x 128] bf16 tile (row-major) into smem (stride 136)
template <int ROWS>
__device__ __forceinline__ void ld_async(bf16* dst, const bf16* __restrict__ src,
                                         size_t row0, int ld, int k0, int tid) {
#pragma unroll
    for (int i = tid; i < ROWS * 16; i += 256) {
        int r = i >> 4, c = i & 15;
        cp16(dst + r * 136 + c * 8, src + (row0 + (size_t)r) * (size_t)ld + k0 + c * 8);
    }
}

// 16-CTA group barrier
__device__ __forceinline__ void group_barrier(int g, int tid) {
    __syncthreads();
    if (tid == 0) {
        volatile unsigned* vg = &g_ggen[g * 32];
        unsigned* cnt = &g_gcnt[g * 32];
        unsigned gen = *vg;
        __threadfence();
        unsigned old = atomicAdd(cnt, 1u);
        if (old == 15u) {
            atomicExch(cnt, 0u);
            __threadfence();
            *vg = gen + 1;
        } else {
            while (*vg == gen) {}
        }
        __threadfence();
    }
    __syncthreads();
}

// ---------------- prep kernels ----------------------------------------------
__global__ void split_kernel(const float* __restrict__ x, bf16* __restrict__ h,
                             bf16* __restrict__ l, size_t n) {
    size_t i = (size_t)blockIdx.x * 256 + threadIdx.x;
    if (i < n) {
        float v = x[i];
        bf16 a = __float2bfloat16(v);
        h[i] = a;
        l[i] = __float2bfloat16(v - __bfloat162float(a));
    }
}
__global__ void transpose_split(const float* __restrict__ W, bf16* __restrict__ Th,
                                bf16* __restrict__ Tl, int K, int N) {
    int idx = blockIdx.x * 256 + threadIdx.x;
    if (idx < N * K) {
        int n = idx / K, k = idx % K;
        float v = W[k * N + n];
        bf16 a = __float2bfloat16(v);
        Th[idx] = a;
        Tl[idx] = __float2bfloat16(v - __bfloat162float(a));
    }
}

// ---------------- phase-1 GEMM: out = act(A @ W^T + bias) -------------------
#define P1_STR 72
#define P1_SA_H 0
#define P1_SA_L (128 * P1_STR)
#define P1_SB_H (2 * 128 * P1_STR)
#define P1_SB_L (3 * 128 * P1_STR)
#define P1_SMEM (4 * 128 * P1_STR * 2)

template <int ROWS, int KCH>
__device__ __forceinline__ void ld_tile(bf16* dst, const bf16* __restrict__ src,
                                        size_t row0, int ld, int k0, int tid) {
    constexpr int STR = KCH + 8;
#pragma unroll
    for (int i = tid; i < ROWS * KCH / 8; i += 256) {
        int r = i / (KCH / 8), c = i % (KCH / 8);
        *(uint4*)(dst + r * STR + c * 8) =
            *(const uint4*)(src + (row0 + (size_t)r) * (size_t)ld + k0 + c * 8);
    }
}

__global__ __launch_bounds__(256) void ff_mma(
    const bf16* __restrict__ Ah, const bf16* __restrict__ Al,
    const bf16* __restrict__ Bh, const bf16* __restrict__ Bl,
    const float* __restrict__ bias, float* __restrict__ outF,
    bf16* __restrict__ outH, bf16* __restrict__ outL,
    int K, int N, int relu_split)
{
    extern __shared__ bf16 sm[];
    const int tid = threadIdx.x, lane = tid & 31, wid = tid >> 5;
    const int wm = wid & 3, wn = wid >> 2;
    const size_t rowBase = (size_t)blockIdx.y * 128;
    const int colBase = blockIdx.x * 128;

    float acc[2][8][4];
#pragma unroll
    for (int i = 0; i < 2; i++)
#pragma unroll
        for (int j = 0; j < 8; j++)
#pragma unroll
            for (int q = 0; q < 4; q++) acc[i][j][q] = 0.f;

    for (int kc = 0; kc < K; kc += 64) {
        ld_tile<128, 64>(sm + P1_SA_H, Ah, rowBase, K, kc, tid);
        ld_tile<128, 64>(sm + P1_SA_L, Al, rowBase, K, kc, tid);
        ld_tile<128, 64>(sm + P1_SB_H, Bh, (size_t)colBase, K, kc, tid);
        ld_tile<128, 64>(sm + P1_SB_L, Bl, (size_t)colBase, K, kc, tid);
        __syncthreads();
#pragma unroll
        for (int ks = 0; ks < 4; ks++) {
            int ko = ks * 16;
            uint32_t ah[2][4], al[2][4];
#pragma unroll
            for (int mf = 0; mf < 2; mf++) {
                ldsm4(ah[mf], sm + P1_SA_H + (wm * 32 + mf * 16) * P1_STR + ko, P1_STR, lane);
                ldsm4(al[mf], sm + P1_SA_L + (wm * 32 + mf * 16) * P1_STR + ko, P1_STR, lane);
            }
#pragma unroll
            for (int nf = 0; nf < 8; nf++) {
                uint32_t bh[2], bl[2];
                ldsm2(bh, sm + P1_SB_H + (wn * 64 + nf * 8) * P1_STR + ko, P1_STR, lane);
                ldsm2(bl, sm + P1_SB_L + (wn * 64 + nf * 8) * P1_STR + ko, P1_STR, lane);
#pragma unroll
                for (int mf = 0; mf < 2; mf++) {
                    hmma(acc[mf][nf], ah[mf], bh);
                    hmma(acc[mf][nf], ah[mf], bl);
                    hmma(acc[mf][nf], al[mf], bh);
                }
            }
        }
        __syncthreads();
    }

#pragma unroll
    for (int mf = 0; mf < 2; mf++) {
#pragma unroll
        for (int nf = 0; nf < 8; nf++) {
            int cg = colBase + wn * 64 + nf * 8 + (lane & 3) * 2;
            float b0 = bias[cg], b1 = bias[cg + 1];
#pragma unroll
            for (int half = 0; half < 2; half++) {
                size_t rg = rowBase + wm * 32 + mf * 16 + (lane >> 2) + half * 8;
                float v0 = acc[mf][nf][half * 2] + b0;
                float v1 = acc[mf][nf][half * 2 + 1] + b1;
                if (relu_split) {
                    v0 = fmaxf(v0, 0.f);
                    v1 = fmaxf(v1, 0.f);
                    __nv_bfloat162 hv, lv;
                    hv.x = __float2bfloat16(v0);
                    hv.y = __float2bfloat16(v1);
                    lv.x = __float2bfloat16(v0 - __bfloat162float(hv.x));
                    lv.y = __float2bfloat16(v1 - __bfloat162float(hv.y));
                    *(__nv_bfloat162*)&outH[rg * N + cg] = hv;
                    *(__nv_bfloat162*)&outL[rg * N + cg] = lv;
                } else {
                    *(float2*)&outF[rg * N + cg] = make_float2(v0, v1);
                }
            }
        }
    }
}

// ---------------- persistent recurrence: 8 groups x 16 CTAs -----------------
// Phase A: inter = relu(h @ w1h + b1h), CTA tile 32x32, K=1024 (8 chunks)
// Phase B: h' = mask ? tanh(xh_t + inter @ w2h + b2h) : h, tile 32x64, K=512
#define RSTR 136
#define O_AH 0
#define O_AL (32 * RSTR)
#define O_BH (64 * RSTR)
#define O_BL (128 * RSTR)
#define RBUF (192 * RSTR)
#define R_SMEM (2 * RBUF * 2)

__global__ __launch_bounds__(256) void recurrence(
    const float* __restrict__ b1h, const float* __restrict__ b2h,
    const int* __restrict__ lens, float* __restrict__ out)
{
    extern __shared__ bf16 sm[];
    const int tid = threadIdx.x, lane = tid & 31, wid = tid >> 5;
    const int wm = wid & 1, wn = wid >> 1;  // 2 x 4 warp grid
    const int cta = blockIdx.x;
    const int grp = cta >> 4;
    const size_t rbase = (size_t)grp * 32;
    const int cbaseA = (cta & 15) * 32;
    const int cbaseB = (cta & 15) * 64;
    bf16* buf[2] = {sm, sm + RBUF};

    // zero h rows of this group (each of 16 CTAs does 1/16)
    for (int i = tid; i < 32 * H_ / 16; i += 256) {
        int j = (int)rbase * H_ + (cta & 15) * (32 * H_ / 16) + i;
        g_h[j] = 0.f;
        g_hh[j] = __float2bfloat16(0.f);
        g_hl[j] = __float2bfloat16(0.f);
    }
    __threadfence();

    // prologue: weights for phase A chunk0 (barrier-independent), then barrier
    ld_async<32>(buf[0] + O_BH, g_w1hTh, (size_t)cbaseA, H_, 0, tid);
    ld_async<32>(buf[0] + O_BL, g_w1hTl, (size_t)cbaseA, H_, 0, tid);
    CP_COMMIT();
    group_barrier(grp, tid);
    ld_async<32>(buf[0] + O_AH, g_hh, rbase, H_, 0, tid);
    ld_async<32>(buf[0] + O_AL, g_hl, rbase, H_, 0, tid);
    CP_COMMIT();

    for (int t = 0; t < S_; t++) {
        // ================= phase A =================
        float accA[4] = {0.f, 0.f, 0.f, 0.f};
        for (int kc = 0; kc < 8; kc++) {
            if (kc < 7) {
                bf16* nb = buf[(kc + 1) & 1];
                int k0 = (kc + 1) * 128;
                ld_async<32>(nb + O_AH, g_hh, rbase, H_, k0, tid);
                ld_async<32>(nb + O_AL, g_hl, rbase, H_, k0, tid);
                ld_async<32>(nb + O_BH, g_w1hTh, (size_t)cbaseA, H_, k0, tid);
                ld_async<32>(nb + O_BL, g_w1hTl, (size_t)cbaseA, H_, k0, tid);
                CP_COMMIT();
                CP_WAIT(1);
            } else {
                CP_WAIT(0);
            }
            __syncthreads();
            bf16* cb = buf[kc & 1];
#pragma unroll
            for (int ks = 0; ks < 8; ks++) {
                int ko = ks * 16;
                uint32_t ah[4], al[4], bh[2], bl[2];
                ldsm4(ah, cb + O_AH + wm * 16 * RSTR + ko, RSTR, lane);
                ldsm4(al, cb + O_AL + wm * 16 * RSTR + ko, RSTR, lane);
                ldsm2(bh, cb + O_BH + wn * 8 * RSTR + ko, RSTR, lane);
                ldsm2(bl, cb + O_BL + wn * 8 * RSTR + ko, RSTR, lane);
                hmma(accA, ah, bh);
                hmma(accA, ah, bl);
                hmma(accA, al, bh);
            }
            __syncthreads();
        }
        {   // epilogue A: relu + split -> g_ih/g_il
            int cg = cbaseA + wn * 8 + (lane & 3) * 2;
            float b0 = b1h[cg], b1 = b1h[cg + 1];
#pragma unroll
            for (int half = 0; half < 2; half++) {
                size_t rg = rbase + wm * 16 + (lane >> 2) + half * 8;
                float v0 = fmaxf(accA[half * 2] + b0, 0.f);
                float v1 = fmaxf(accA[half * 2 + 1] + b1, 0.f);
                __nv_bfloat162 hv, lv;
                hv.x = __float2bfloat16(v0);
                hv.y = __float2bfloat16(v1);
                lv.x = __float2bfloat16(v0 - __bfloat162float(hv.x));
                lv.y = __float2bfloat16(v1 - __bfloat162float(hv.y));
                *(__nv_bfloat162*)&g_ih[rg * HH_ + cg] = hv;
                *(__nv_bfloat162*)&g_il[rg * HH_ + cg] = lv;
            }
            __threadfence();
        }
        // pre-issue phase-B weights chunk0 (buf0 free: last compute was buf1)
        ld_async<64>(buf[0] + O_BH, g_w2hTh, (size_t)cbaseB, HH_, 0, tid);
        ld_async<64>(buf[0] + O_BL, g_w2hTl, (size_t)cbaseB, HH_, 0, tid);
        CP_COMMIT();
        group_barrier(grp, tid);
        ld_async<32>(buf[0] + O_AH, g_ih, rbase, HH_, 0, tid);
        ld_async<32>(buf[0] + O_AL, g_il, rbase, HH_, 0, tid);
        CP_COMMIT();

        // ================= phase B =================
        float accB[2][4];
#pragma unroll
        for (int i = 0; i < 2; i++)
#pragma unroll
            for (int j = 0; j < 4; j++) accB[i][j] = 0.f;
        for (int kc = 0; kc < 4; kc++) {
            if (kc < 3) {
                bf16* nb = buf[(kc + 1) & 1];
                int k0 = (kc + 1) * 128;
                ld_async<32>(nb + O_AH, g_ih, rbase, HH_, k0, tid);
                ld_async<32>(nb + O_AL, g_il, rbase, HH_, k0, tid);
                ld_async<64>(nb + O_BH, g_w2hTh, (size_t)cbaseB, HH_, k0, tid);
                ld_async<64>(nb + O_BL, g_w2hTl, (size_t)cbaseB, HH_, k0, tid);
                CP_COMMIT();
                CP_WAIT(1);
            } else {
                CP_WAIT(0);
            }
            __syncthreads();
            bf16* cb = buf[kc & 1];
#pragma unroll
            for (int ks = 0; ks < 8; ks++) {
                int ko = ks * 16;
                uint32_t ah[4], al[4];
                ldsm4(ah, cb + O_AH + wm * 16 * RSTR + ko, RSTR, lane);
                ldsm4(al, cb + O_AL + wm * 16 * RSTR + ko, RSTR, lane);
#pragma unroll
                for (int nf = 0; nf < 2; nf++) {
                    uint32_t bh[2], bl[2];
                    ldsm2(bh, cb + O_BH + (wn * 16 + nf * 8) * RSTR + ko, RSTR, lane);
                    ldsm2(bl, cb + O_BL + (wn * 16 + nf * 8) * RSTR + ko, RSTR, lane);
                    hmma(accB[nf], ah, bh);
                    hmma(accB[nf], ah, bl);
                    hmma(accB[nf], al, bh);
                }
            }
            __syncthreads();
        }
        {   // epilogue B: tanh + mask; write out, g_h, split state
#pragma unroll
            for (int half = 0; half < 2; half++) {
                size_t rg = rbase + wm * 16 + (lane >> 2) + half * 8;
                const bool on = (t < lens[rg]);
#pragma unroll
                for (int nf = 0; nf < 2; nf++) {
                    int cg = cbaseB + wn * 16 + nf * 8 + (lane & 3) * 2;
                    float v0, v1;
                    if (on) {
                        float2 xv = *(const float2*)&g_xh[(rg * S_ + t) * H_ + cg];
                        v0 = fast_tanh(xv.x + accB[nf][half * 2] + b2h[cg]);
                        v1 = fast_tanh(xv.y + accB[nf][half * 2 + 1] + b2h[cg + 1]);
                    } else {
                        float2 pv = *(const float2*)&g_h[rg * H_ + cg];
                        v0 = pv.x;
                        v1 = pv.y;
                    }
                    *(float2*)&g_h[rg * H_ + cg] = make_float2(v0, v1);
                    *(float2*)&out[(rg * S_ + t) * H_ + cg] = make_float2(v0, v1);
                    __nv_bfloat162 hv, lv;
                    hv.x = __float2bfloat16(v0);
                    hv.y = __float2bfloat16(v1);
                    lv.x = __float2bfloat16(v0 - __bfloat162float(hv.x));
                    lv.y = __float2bfloat16(v1 - __bfloat162float(hv.y));
                    *(__nv_bfloat162*)&g_hh[rg * H_ + cg] = hv;
                    *(__nv_bfloat162*)&g_hl[rg * H_ + cg] = lv;
                }
            }
            __threadfence();
        }
        if (t < S_ - 1) {
            // pre-issue next phase-A weights chunk0, then barrier, then A tiles
            ld_async<32>(buf[0] + O_BH, g_w1hTh, (size_t)cbaseA, H_, 0, tid);
            ld_async<32>(buf[0] + O_BL, g_w1hTl, (size_t)cbaseA, H_, 0, tid);
            CP_COMMIT();
            group_barrier(grp, tid);
            ld_async<32>(buf[0] + O_AH, g_hh, rbase, H_, 0, tid);
            ld_async<32>(buf[0] + O_AL, g_hl, rbase, H_, 0, tid);
            CP_COMMIT();
        }
    }
}

// ---------------- launcher --------------------------------------------------
extern "C" void kernel_launch(void* const* d_in, const int* in_sizes, int n_in,
                              void* d_out, int out_size) {
    const float* seq = (const float*)d_in[0];
    const int* lens  = (const int*)d_in[1];
    const float* w1x = (const float*)d_in[2];
    const float* b1x = (const float*)d_in[3];
    const float* w2x = (const float*)d_in[4];
    const float* b2x = (const float*)d_in[5];
    const float* w1h = (const float*)d_in[6];
    const float* b1h = (const float*)d_in[7];
    const float* w2h = (const float*)d_in[8];
    const float* b2h = (const float*)d_in[9];
    float* out = (float*)d_out;

    bf16 *seqh, *seql, *tmph, *tmpl;
    bf16 *w1xh, *w1xl, *w2xh, *w2xl, *w1hh, *w1hl, *w2hh, *w2hl;
    float* xh;
    cudaGetSymbolAddress((void**)&seqh, g_seqh);
    cudaGetSymbolAddress((void**)&seql, g_seql);
    cudaGetSymbolAddress((void**)&tmph, g_tmph);
    cudaGetSymbolAddress((void**)&tmpl, g_tmpl);
    cudaGetSymbolAddress((void**)&xh, g_xh);
    cudaGetSymbolAddress((void**)&w1xh, g_w1xTh);
    cudaGetSymbolAddress((void**)&w1xl, g_w1xTl);
    cudaGetSymbolAddress((void**)&w2xh, g_w2xTh);
    cudaGetSymbolAddress((void**)&w2xl, g_w2xTl);
    cudaGetSymbolAddress((void**)&w1hh, g_w1hTh);
    cudaGetSymbolAddress((void**)&w1hl, g_w1hTl);
    cudaGetSymbolAddress((void**)&w2hh, g_w2hTh);
    cudaGetSymbolAddress((void**)&w2hl, g_w2hTl);

    cudaFuncSetAttribute(ff_mma, cudaFuncAttributeMaxDynamicSharedMemorySize, P1_SMEM);
    cudaFuncSetAttribute(recurrence, cudaFuncAttributeMaxDynamicSharedMemorySize, R_SMEM);

    size_t nseq = (size_t)MTOK * E_;
    split_kernel<<<(unsigned)((nseq + 255) / 256), 256>>>(seq, seqh, seql, nseq);
    transpose_split<<<(E_ * HH_ + 255) / 256, 256>>>(w1x, w1xh, w1xl, E_, HH_);
    transpose_split<<<(HH_ * H_ + 255) / 256, 256>>>(w2x, w2xh, w2xl, HH_, H_);
    transpose_split<<<(H_ * HH_ + 255) / 256, 256>>>(w1h, w1hh, w1hl, H_, HH_);
    transpose_split<<<(HH_ * H_ + 255) / 256, 256>>>(w2h, w2hh, w2hl, HH_, H_);

    ff_mma<<<dim3(HH_ / 128, MTOK / 128), 256, P1_SMEM>>>(
        seqh, seql, w1xh, w1xl, b1x, nullptr, tmph, tmpl, E_, HH_, 1);
    ff_mma<<<dim3(H_ / 128, MTOK / 128), 256, P1_SMEM>>>(
        tmph, tmpl, w2xh, w2xl, b2x, xh, nullptr, nullptr, HH_, H_, 0);

    recurrence<<<128, 256, R_SMEM>>>(b1h, b2h, lens, out);
}

// round 7
// speedup vs baseline: 3.3401x; 1.1828x over previous
#include <cuda_runtime.h>
#include <cuda_bf16.h>
#include <cstdint>

#define B_ 256
#define S_ 512
#define E_ 512
#define H_ 1024
#define HH_ 512
#define MTOK (B_ * S_)

typedef __nv_bfloat16 bf16;

// ---------------- device-global scratch ------------------------------------
__device__ bf16 g_seqh[(size_t)MTOK * E_];
__device__ bf16 g_seql[(size_t)MTOK * E_];
__device__ bf16 g_tmph[(size_t)MTOK * HH_];
__device__ bf16 g_tmpl[(size_t)MTOK * HH_];
__device__ float g_xh[(size_t)MTOK * H_];
__device__ bf16 g_w1xTh[HH_ * E_], g_w1xTl[HH_ * E_];   // [N,K]
__device__ bf16 g_w2xTh[H_ * HH_], g_w2xTl[H_ * HH_];
__device__ bf16 g_w1hTh[HH_ * H_], g_w1hTl[HH_ * H_];
__device__ bf16 g_w2hTh[H_ * HH_], g_w2hTl[H_ * HH_];
__device__ bf16 g_hh[B_ * H_], g_hl[B_ * H_];
__device__ bf16 g_ih[B_ * HH_], g_il[B_ * HH_];
__device__ unsigned g_gcnt[8 * 32];
__device__ volatile unsigned g_ggen[8 * 32];

// ---------------- helpers ----------------------------------------------------
__device__ __forceinline__ uint32_t smem_u32(const void* p) {
    uint32_t r;
    asm("{ .reg .u64 t; cvta.to.shared.u64 t, %1; cvt.u32.u64 %0, t; }" : "=r"(r) : "l"(p));
    return r;
}
__device__ __forceinline__ float fast_tanh(float x) {
    float y; asm("tanh.approx.f32 %0, %1;" : "=f"(y) : "f"(x)); return y;
}
__device__ __forceinline__ void hmma(float c[4], const uint32_t a[4], const uint32_t b[2]) {
    asm volatile("mma.sync.aligned.m16n8k16.row.col.f32.bf16.bf16.f32 "
        "{%0,%1,%2,%3}, {%4,%5,%6,%7}, {%8,%9}, {%0,%1,%2,%3};"
        : "+f"(c[0]), "+f"(c[1]), "+f"(c[2]), "+f"(c[3])
        : "r"(a[0]), "r"(a[1]), "r"(a[2]), "r"(a[3]), "r"(b[0]), "r"(b[1]));
}
// swizzled ldmatrix: tile rows of `rowlen` bf16, 16B segs XORed with (row&7)
__device__ __forceinline__ void ldsm4_s(uint32_t a[4], const bf16* tb, int rowlen,
                                        int rowbase, int ko, int lane) {
    int row = rowbase + (lane & 15);
    int seg = (ko >> 3) + (lane >> 4);
    uint32_t addr = smem_u32(tb + row * rowlen + ((seg ^ (row & 7)) << 3));
    asm volatile("ldmatrix.sync.aligned.m8n8.x4.shared.b16 {%0,%1,%2,%3}, [%4];"
        : "=r"(a[0]), "=r"(a[1]), "=r"(a[2]), "=r"(a[3]) : "r"(addr));
}
__device__ __forceinline__ void ldsm2_s(uint32_t b[2], const bf16* tb, int rowlen,
                                        int rowbase, int ko, int lane) {
    int row = rowbase + (lane & 7);
    int seg = (ko >> 3) + ((lane >> 3) & 1);
    uint32_t addr = smem_u32(tb + row * rowlen + ((seg ^ (row & 7)) << 3));
    asm volatile("ldmatrix.sync.aligned.m8n8.x2.shared.b16 {%0,%1}, [%2];"
        : "=r"(b[0]), "=r"(b[1]) : "r"(addr));
}
__device__ __forceinline__ void cp16(bf16* s, const bf16* g) {
    uint32_t sa = smem_u32(s);
    asm volatile("cp.async.cg.shared.global [%0], [%1], 16;" :: "r"(sa), "l"(g));
}
#define CP_COMMIT() asm volatile("cp.async.commit_group;" ::: "memory")
#define CP_WAIT(n) asm volatile("cp.async.wait_group %0;" :: "n"(n) : "memory")

// async-load [ROWS x SEGS*8] bf16 tile, swizzled
template <int ROWS, int SEGS>
__device__ __forceinline__ void ld_sw(bf16* dst, const bf16* __restrict__ src,
                                      size_t row0, int ld, int k0, int tid) {
#pragma unroll
    for (int i = tid; i < ROWS * SEGS; i += 256) {
        int r = i / SEGS, c = i % SEGS;
        cp16(dst + r * SEGS * 8 + ((c ^ (r & 7)) << 3),
             src + (row0 + (size_t)r) * (size_t)ld + k0 + c * 8);
    }
}

__device__ __forceinline__ void group_barrier(int g, int tid) {
    __syncthreads();
    if (tid == 0) {
        volatile unsigned* vg = &g_ggen[g * 32];
        unsigned* cnt = &g_gcnt[g * 32];
        unsigned gen = *vg;
        __threadfence();
        unsigned old = atomicAdd(cnt, 1u);
        if (old == 15u) {
            atomicExch(cnt, 0u);
            __threadfence();
            *vg = gen + 1;
        } else {
            while (*vg == gen) {}
        }
        __threadfence();
    }
    __syncthreads();
}

// ---------------- prep kernels ----------------------------------------------
__global__ void split_kernel(const float* __restrict__ x, bf16* __restrict__ h,
                             bf16* __restrict__ l, size_t n) {
    size_t i = (size_t)blockIdx.x * 256 + threadIdx.x;
    if (i < n) {
        float v = x[i];
        bf16 a = __float2bfloat16(v);
        h[i] = a;
        l[i] = __float2bfloat16(v - __bfloat162float(a));
    }
}
__global__ void transpose_split(const float* __restrict__ W, bf16* __restrict__ Th,
                                bf16* __restrict__ Tl, int K, int N) {
    int idx = blockIdx.x * 256 + threadIdx.x;
    if (idx < N * K) {
        int n = idx / K, k = idx % K;
        float v = W[k * N + n];
        bf16 a = __float2bfloat16(v);
        Th[idx] = a;
        Tl[idx] = __float2bfloat16(v - __bfloat162float(a));
    }
}

// ---------------- phase-1 GEMM: out = act(A @ W^T + bias) -------------------
// Tile 128x128, K-chunk 64, double-buffered cp.async. 8 warps (4m x 2n).
#define P1_AH 0
#define P1_AL 8192
#define P1_BH 16384
#define P1_BL 24576
#define P1_BUF 32768
#define P1_SMEM (2 * P1_BUF * 2)

__global__ __launch_bounds__(256) void ff_mma(
    const bf16* __restrict__ Ah, const bf16* __restrict__ Al,
    const bf16* __restrict__ Bh, const bf16* __restrict__ Bl,
    const float* __restrict__ bias, float* __restrict__ outF,
    bf16* __restrict__ outH, bf16* __restrict__ outL,
    int K, int N, int relu_split)
{
    extern __shared__ bf16 sm[];
    bf16* buf[2] = {sm, sm + P1_BUF};
    const int tid = threadIdx.x, lane = tid & 31, wid = tid >> 5;
    const int wm = wid & 3, wn = wid >> 2;
    const size_t rowBase = (size_t)blockIdx.y * 128;
    const int colBase = blockIdx.x * 128;
    const int nch = K / 64;

    float acc[2][8][4];
#pragma unroll
    for (int i = 0; i < 2; i++)
#pragma unroll
        for (int j = 0; j < 8; j++)
#pragma unroll
            for (int q = 0; q < 4; q++) acc[i][j][q] = 0.f;

    ld_sw<128, 8>(buf[0] + P1_AH, Ah, rowBase, K, 0, tid);
    ld_sw<128, 8>(buf[0] + P1_AL, Al, rowBase, K, 0, tid);
    ld_sw<128, 8>(buf[0] + P1_BH, Bh, (size_t)colBase, K, 0, tid);
    ld_sw<128, 8>(buf[0] + P1_BL, Bl, (size_t)colBase, K, 0, tid);
    CP_COMMIT();

    for (int kc = 0; kc < nch; kc++) {
        if (kc < nch - 1) {
            bf16* nb = buf[(kc + 1) & 1];
            int k0 = (kc + 1) * 64;
            ld_sw<128, 8>(nb + P1_AH, Ah, rowBase, K, k0, tid);
            ld_sw<128, 8>(nb + P1_AL, Al, rowBase, K, k0, tid);
            ld_sw<128, 8>(nb + P1_BH, Bh, (size_t)colBase, K, k0, tid);
            ld_sw<128, 8>(nb + P1_BL, Bl, (size_t)colBase, K, k0, tid);
            CP_COMMIT();
            CP_WAIT(1);
        } else {
            CP_WAIT(0);
        }
        __syncthreads();
        bf16* cb = buf[kc & 1];
#pragma unroll
        for (int ks = 0; ks < 4; ks++) {
            int ko = ks * 16;
            uint32_t ah[2][4], al[2][4];
#pragma unroll
            for (int mf = 0; mf < 2; mf++) {
                ldsm4_s(ah[mf], cb + P1_AH, 64, wm * 32 + mf * 16, ko, lane);
                ldsm4_s(al[mf], cb + P1_AL, 64, wm * 32 + mf * 16, ko, lane);
            }
#pragma unroll
            for (int nf = 0; nf < 8; nf++) {
                uint32_t bh[2], bl[2];
                ldsm2_s(bh, cb + P1_BH, 64, wn * 64 + nf * 8, ko, lane);
                ldsm2_s(bl, cb + P1_BL, 64, wn * 64 + nf * 8, ko, lane);
#pragma unroll
                for (int mf = 0; mf < 2; mf++) {
                    hmma(acc[mf][nf], ah[mf], bh);
                    hmma(acc[mf][nf], ah[mf], bl);
                    hmma(acc[mf][nf], al[mf], bh);
                }
            }
        }
        __syncthreads();
    }

#pragma unroll
    for (int mf = 0; mf < 2; mf++) {
#pragma unroll
        for (int nf = 0; nf < 8; nf++) {
            int cg = colBase + wn * 64 + nf * 8 + (lane & 3) * 2;
            float b0 = bias[cg], b1 = bias[cg + 1];
#pragma unroll
            for (int half = 0; half < 2; half++) {
                size_t rg = rowBase + wm * 32 + mf * 16 + (lane >> 2) + half * 8;
                float v0 = acc[mf][nf][half * 2] + b0;
                float v1 = acc[mf][nf][half * 2 + 1] + b1;
                if (relu_split) {
                    v0 = fmaxf(v0, 0.f);
                    v1 = fmaxf(v1, 0.f);
                    __nv_bfloat162 hv, lv;
                    hv.x = __float2bfloat16(v0);
                    hv.y = __float2bfloat16(v1);
                    lv.x = __float2bfloat16(v0 - __bfloat162float(hv.x));
                    lv.y = __float2bfloat16(v1 - __bfloat162float(hv.y));
                    *(__nv_bfloat162*)&outH[rg * N + cg] = hv;
                    *(__nv_bfloat162*)&outL[rg * N + cg] = lv;
                } else {
                    *(float2*)&outF[rg * N + cg] = make_float2(v0, v1);
                }
            }
        }
    }
}

// ---------------- persistent recurrence: 8 groups x 16 CTAs -----------------
// Resident in smem: this CTA's w1h slice (32 cols x K=1024, hi+lo) = 128 KB.
// Phase A: inter = relu(h @ w1h + b1h), tile 32x32, stream h (hi/lo) chunks.
// Phase B: h' = mask ? tanh(xh_t + inter @ w2h + b2h) : h, tile 32x64,
//          stream inter + w2h chunks. h kept in registers for masked rows.
#define RW_H 0
#define RW_L 32768
#define R_SB 65536
#define RO_AH 0
#define RO_AL 4096
#define RO_WH 8192
#define RO_WL 16384
#define R_BUF 24576
#define R_SMEM ((R_SB + 2 * R_BUF) * 2)

__global__ __launch_bounds__(256) void recurrence(
    const float* __restrict__ b1h, const float* __restrict__ b2h,
    const int* __restrict__ lens, float* __restrict__ out)
{
    extern __shared__ bf16 sm[];
    bf16* smWH = sm + RW_H;
    bf16* smWL = sm + RW_L;
    bf16* buf[2] = {sm + R_SB, sm + R_SB + R_BUF};
    const int tid = threadIdx.x, lane = tid & 31, wid = tid >> 5;
    const int wm = wid & 1, wn = wid >> 1;  // 2m x 4n warps
    const int cta = blockIdx.x;
    const int grp = cta >> 4;
    const size_t rbase = (size_t)grp * 32;
    const int cbaseA = (cta & 15) * 32;
    const int cbaseB = (cta & 15) * 64;

    // zero split h state (replayed graph)
    for (int i = tid; i < 2048; i += 256) {
        int j = (int)rbase * H_ + (cta & 15) * 2048 + i;
        g_hh[j] = __float2bfloat16(0.f);
        g_hl[j] = __float2bfloat16(0.f);
    }
    __threadfence();

    // resident phase-A weights (once)
    for (int i = tid; i < 32 * 128; i += 256) {
        int r = i >> 7, c = i & 127;
        int d = r * 1024 + ((c ^ (r & 7)) << 3);
        *(uint4*)(smWH + d) = *(const uint4*)&g_w1hTh[(size_t)(cbaseA + r) * H_ + c * 8];
        *(uint4*)(smWL + d) = *(const uint4*)&g_w1hTl[(size_t)(cbaseA + r) * H_ + c * 8];
    }
    group_barrier(grp, tid);

    // per-thread constants
    const size_t rg0 = rbase + wm * 16 + (lane >> 2);
    const size_t rg1 = rg0 + 8;
    const int len0 = lens[rg0], len1 = lens[rg1];
    const int cgA = cbaseA + wn * 8 + (lane & 3) * 2;
    const float pb1_0 = b1h[cgA], pb1_1 = b1h[cgA + 1];
    float pb2[2][2];
#pragma unroll
    for (int nf = 0; nf < 2; nf++) {
        int cg = cbaseB + wn * 16 + nf * 8 + (lane & 3) * 2;
        pb2[nf][0] = b2h[cg];
        pb2[nf][1] = b2h[cg + 1];
    }
    float h_prev[2][4];
#pragma unroll
    for (int nf = 0; nf < 2; nf++)
#pragma unroll
        for (int q = 0; q < 4; q++) h_prev[nf][q] = 0.f;

    for (int t = 0; t < S_; t++) {
        // ================= phase A =================
        float accA[3][4];
#pragma unroll
        for (int i = 0; i < 3; i++)
#pragma unroll
            for (int q = 0; q < 4; q++) accA[i][q] = 0.f;

        ld_sw<32, 16>(buf[0] + RO_AH, g_hh, rbase, H_, 0, tid);
        ld_sw<32, 16>(buf[0] + RO_AL, g_hl, rbase, H_, 0, tid);
        CP_COMMIT();
        for (int kc = 0; kc < 8; kc++) {
            if (kc < 7) {
                bf16* nb = buf[(kc + 1) & 1];
                int k0 = (kc + 1) * 128;
                ld_sw<32, 16>(nb + RO_AH, g_hh, rbase, H_, k0, tid);
                ld_sw<32, 16>(nb + RO_AL, g_hl, rbase, H_, k0, tid);
                CP_COMMIT();
                CP_WAIT(1);
            } else {
                CP_WAIT(0);
            }
            __syncthreads();
            bf16* cb = buf[kc & 1];
#pragma unroll
            for (int ks = 0; ks < 8; ks++) {
                int ko = ks * 16;
                uint32_t ah[4], al[4], bh[2], bl[2];
                ldsm4_s(ah, cb + RO_AH, 128, wm * 16, ko, lane);
                ldsm4_s(al, cb + RO_AL, 128, wm * 16, ko, lane);
                ldsm2_s(bh, smWH, 1024, wn * 8, kc * 128 + ko, lane);
                ldsm2_s(bl, smWL, 1024, wn * 8, kc * 128 + ko, lane);
                hmma(accA[0], ah, bh);
                hmma(accA[1], ah, bl);
                hmma(accA[2], al, bh);
            }
            __syncthreads();
        }
        // pre-issue phase-B weight chunk0 (W slots, disjoint from A slots)
        ld_sw<64, 16>(buf[0] + RO_WH, g_w2hTh, (size_t)cbaseB, HH_, 0, tid);
        ld_sw<64, 16>(buf[0] + RO_WL, g_w2hTl, (size_t)cbaseB, HH_, 0, tid);
        CP_COMMIT();
        // epilogue A
        {
#pragma unroll
            for (int half = 0; half < 2; half++) {
                size_t rg = (half == 0) ? rg0 : rg1;
                float v0 = fmaxf(accA[0][half * 2] + accA[1][half * 2] +
                                 accA[2][half * 2] + pb1_0, 0.f);
                float v1 = fmaxf(accA[0][half * 2 + 1] + accA[1][half * 2 + 1] +
                                 accA[2][half * 2 + 1] + pb1_1, 0.f);
                __nv_bfloat162 hv, lv;
                hv.x = __float2bfloat16(v0);
                hv.y = __float2bfloat16(v1);
                lv.x = __float2bfloat16(v0 - __bfloat162float(hv.x));
                lv.y = __float2bfloat16(v1 - __bfloat162float(hv.y));
                *(__nv_bfloat162*)&g_ih[rg * HH_ + cgA] = hv;
                *(__nv_bfloat162*)&g_il[rg * HH_ + cgA] = lv;
            }
        }
        __threadfence();
        group_barrier(grp, tid);

        // ================= phase B =================
        float accB[2][3][4];
#pragma unroll
        for (int nf = 0; nf < 2; nf++)
#pragma unroll
            for (int i = 0; i < 3; i++)
#pragma unroll
                for (int q = 0; q < 4; q++) accB[nf][i][q] = 0.f;

        ld_sw<32, 16>(buf[0] + RO_AH, g_ih, rbase, HH_, 0, tid);
        ld_sw<32, 16>(buf[0] + RO_AL, g_il, rbase, HH_, 0, tid);
        CP_COMMIT();
        for (int kc = 0; kc < 4; kc++) {
            if (kc < 3) {
                bf16* nb = buf[(kc + 1) & 1];
                int k0 = (kc + 1) * 128;
                ld_sw<32, 16>(nb + RO_AH, g_ih, rbase, HH_, k0, tid);
                ld_sw<32, 16>(nb + RO_AL, g_il, rbase, HH_, k0, tid);
                ld_sw<64, 16>(nb + RO_WH, g_w2hTh, (size_t)cbaseB, HH_, k0, tid);
                ld_sw<64, 16>(nb + RO_WL, g_w2hTl, (size_t)cbaseB, HH_, k0, tid);
                CP_COMMIT();
                CP_WAIT(1);
            } else {
                CP_WAIT(0);
            }
            __syncthreads();
            bf16* cb = buf[kc & 1];
#pragma unroll
            for (int ks = 0; ks < 8; ks++) {
                int ko = ks * 16;
                uint32_t ah[4], al[4];
                ldsm4_s(ah, cb + RO_AH, 128, wm * 16, ko, lane);
                ldsm4_s(al, cb + RO_AL, 128, wm * 16, ko, lane);
#pragma unroll
                for (int nf = 0; nf < 2; nf++) {
                    uint32_t bh[2], bl[2];
                    ldsm2_s(bh, cb + RO_WH, 128, wn * 16 + nf * 8, ko, lane);
                    ldsm2_s(bl, cb + RO_WL, 128, wn * 16 + nf * 8, ko, lane);
                    hmma(accB[nf][0], ah, bh);
                    hmma(accB[nf][1], ah, bl);
                    hmma(accB[nf][2], al, bh);
                }
            }
            __syncthreads();
        }
        // epilogue B
#pragma unroll
        for (int nf = 0; nf < 2; nf++) {
            int cg = cbaseB + wn * 16 + nf * 8 + (lane & 3) * 2;
#pragma unroll
            for (int half = 0; half < 2; half++) {
                size_t rg = (half == 0) ? rg0 : rg1;
                bool on = t < ((half == 0) ? len0 : len1);
                float v0, v1;
                if (on) {
                    float2 xv = *(const float2*)&g_xh[(rg * S_ + t) * H_ + cg];
                    float s0 = accB[nf][0][half * 2] + accB[nf][1][half * 2] +
                               accB[nf][2][half * 2];
                    float s1 = accB[nf][0][half * 2 + 1] + accB[nf][1][half * 2 + 1] +
                               accB[nf][2][half * 2 + 1];
                    v0 = fast_tanh(xv.x + s0 + pb2[nf][0]);
                    v1 = fast_tanh(xv.y + s1 + pb2[nf][1]);
                    h_prev[nf][half * 2] = v0;
                    h_prev[nf][half * 2 + 1] = v1;
                    __nv_bfloat162 hv, lv;
                    hv.x = __float2bfloat16(v0);
                    hv.y = __float2bfloat16(v1);
                    lv.x = __float2bfloat16(v0 - __bfloat162float(hv.x));
                    lv.y = __float2bfloat16(v1 - __bfloat162float(hv.y));
                    *(__nv_bfloat162*)&g_hh[rg * H_ + cg] = hv;
                    *(__nv_bfloat162*)&g_hl[rg * H_ + cg] = lv;
                } else {
                    v0 = h_prev[nf][half * 2];
                    v1 = h_prev[nf][half * 2 + 1];
                }
                *(float2*)&out[(rg * S_ + t) * H_ + cg] = make_float2(v0, v1);
            }
        }
        __threadfence();
        group_barrier(grp, tid);
    }
}

// ---------------- launcher --------------------------------------------------
extern "C" void kernel_launch(void* const* d_in, const int* in_sizes, int n_in,
                              void* d_out, int out_size) {
    const float* seq = (const float*)d_in[0];
    const int* lens  = (const int*)d_in[1];
    const float* w1x = (const float*)d_in[2];
    const float* b1x = (const float*)d_in[3];
    const float* w2x = (const float*)d_in[4];
    const float* b2x = (const float*)d_in[5];
    const float* w1h = (const float*)d_in[6];
    const float* b1h = (const float*)d_in[7];
    const float* w2h = (const float*)d_in[8];
    const float* b2h = (const float*)d_in[9];
    float* out = (float*)d_out;

    bf16 *seqh, *seql, *tmph, *tmpl;
    bf16 *w1xh, *w1xl, *w2xh, *w2xl, *w1hh, *w1hl, *w2hh, *w2hl;
    float* xh;
    cudaGetSymbolAddress((void**)&seqh, g_seqh);
    cudaGetSymbolAddress((void**)&seql, g_seql);
    cudaGetSymbolAddress((void**)&tmph, g_tmph);
    cudaGetSymbolAddress((void**)&tmpl, g_tmpl);
    cudaGetSymbolAddress((void**)&xh, g_xh);
    cudaGetSymbolAddress((void**)&w1xh, g_w1xTh);
    cudaGetSymbolAddress((void**)&w1xl, g_w1xTl);
    cudaGetSymbolAddress((void**)&w2xh, g_w2xTh);
    cudaGetSymbolAddress((void**)&w2xl, g_w2xTl);
    cudaGetSymbolAddress((void**)&w1hh, g_w1hTh);
    cudaGetSymbolAddress((void**)&w1hl, g_w1hTl);
    cudaGetSymbolAddress((void**)&w2hh, g_w2hTh);
    cudaGetSymbolAddress((void**)&w2hl, g_w2hTl);

    cudaFuncSetAttribute(ff_mma, cudaFuncAttributeMaxDynamicSharedMemorySize, P1_SMEM);
    cudaFuncSetAttribute(recurrence, cudaFuncAttributeMaxDynamicSharedMemorySize, R_SMEM);

    size_t nseq = (size_t)MTOK * E_;
    split_kernel<<<(unsigned)((nseq + 255) / 256), 256>>>(seq, seqh, seql, nseq);
    transpose_split<<<(E_ * HH_ + 255) / 256, 256>>>(w1x, w1xh, w1xl, E_, HH_);
    transpose_split<<<(HH_ * H_ + 255) / 256, 256>>>(w2x, w2xh, w2xl, HH_, H_);
    transpose_split<<<(H_ * HH_ + 255) / 256, 256>>>(w1h, w1hh, w1hl, H_, HH_);
    transpose_split<<<(HH_ * H_ + 255) / 256, 256>>>(w2h, w2hh, w2hl, HH_, H_);

    ff_mma<<<dim3(HH_ / 128, MTOK / 128), 256, P1_SMEM>>>(
        seqh, seql, w1xh, w1xl, b1x, nullptr, tmph, tmpl, E_, HH_, 1);
    ff_mma<<<dim3(H_ / 128, MTOK / 128), 256, P1_SMEM>>>(
        tmph, tmpl, w2xh, w2xl, b2x, xh, nullptr, nullptr, HH_, H_, 0);

    recurrence<<<128, 256, R_SMEM>>>(b1h, b2h, lens, out);
}

// round 8
// speedup vs baseline: 3.7750x; 1.1302x over previous
#include <cuda_runtime.h>
#include <cuda_bf16.h>
#include <cstdint>

#define B_ 256
#define S_ 512
#define E_ 512
#define H_ 1024
#define HH_ 512
#define MTOK (B_ * S_)

typedef __nv_bfloat16 bf16;

// ---------------- device-global scratch ------------------------------------
__device__ bf16 g_seqh[(size_t)MTOK * E_];
__device__ bf16 g_seql[(size_t)MTOK * E_];
__device__ bf16 g_tmph[(size_t)MTOK * HH_];
__device__ bf16 g_tmpl[(size_t)MTOK * HH_];
__device__ float g_xh[(size_t)MTOK * H_];
__device__ bf16 g_w1xTh[HH_ * E_], g_w1xTl[HH_ * E_];   // [N,K]
__device__ bf16 g_w2xTh[H_ * HH_], g_w2xTl[H_ * HH_];
__device__ bf16 g_w1hTh[HH_ * H_], g_w1hTl[HH_ * H_];
__device__ bf16 g_w2hTh[H_ * HH_], g_w2hTl[H_ * HH_];
__device__ bf16 g_hh[B_ * H_], g_hl[B_ * H_];
__device__ bf16 g_ih[B_ * HH_], g_il[B_ * HH_];
__device__ unsigned g_gcnt[8 * 32];
__device__ volatile unsigned g_ggen[8 * 32];

// ---------------- helpers ----------------------------------------------------
__device__ __forceinline__ uint32_t smem_u32(const void* p) {
    uint32_t r;
    asm("{ .reg .u64 t; cvta.to.shared.u64 t, %1; cvt.u32.u64 %0, t; }" : "=r"(r) : "l"(p));
    return r;
}
__device__ __forceinline__ float fast_tanh(float x) {
    float y; asm("tanh.approx.f32 %0, %1;" : "=f"(y) : "f"(x)); return y;
}
__device__ __forceinline__ void hmma(float c[4], const uint32_t a[4], const uint32_t b[2]) {
    asm volatile("mma.sync.aligned.m16n8k16.row.col.f32.bf16.bf16.f32 "
        "{%0,%1,%2,%3}, {%4,%5,%6,%7}, {%8,%9}, {%0,%1,%2,%3};"
        : "+f"(c[0]), "+f"(c[1]), "+f"(c[2]), "+f"(c[3])
        : "r"(a[0]), "r"(a[1]), "r"(a[2]), "r"(a[3]), "r"(b[0]), "r"(b[1]));
}
// swizzled ldmatrix: tile rows of `rowlen` bf16, 16B segs XORed with (row&7)
__device__ __forceinline__ void ldsm4_s(uint32_t a[4], const bf16* tb, int rowlen,
                                        int rowbase, int ko, int lane) {
    int row = rowbase + (lane & 15);
    int seg = (ko >> 3) + (lane >> 4);
    uint32_t addr = smem_u32(tb + row * rowlen + ((seg ^ (row & 7)) << 3));
    asm volatile("ldmatrix.sync.aligned.m8n8.x4.shared.b16 {%0,%1,%2,%3}, [%4];"
        : "=r"(a[0]), "=r"(a[1]), "=r"(a[2]), "=r"(a[3]) : "r"(addr));
}
__device__ __forceinline__ void ldsm2_s(uint32_t b[2], const bf16* tb, int rowlen,
                                        int rowbase, int ko, int lane) {
    int row = rowbase + (lane & 7);
    int seg = (ko >> 3) + ((lane >> 3) & 1);
    uint32_t addr = smem_u32(tb + row * rowlen + ((seg ^ (row & 7)) << 3));
    asm volatile("ldmatrix.sync.aligned.m8n8.x2.shared.b16 {%0,%1}, [%2];"
        : "=r"(b[0]), "=r"(b[1]) : "r"(addr));
}
__device__ __forceinline__ void cp16(bf16* s, const bf16* g) {
    uint32_t sa = smem_u32(s);
    asm volatile("cp.async.cg.shared.global [%0], [%1], 16;" :: "r"(sa), "l"(g));
}
#define CP_COMMIT() asm volatile("cp.async.commit_group;" ::: "memory")
#define CP_WAIT(n) asm volatile("cp.async.wait_group %0;" :: "n"(n) : "memory")

// async-load [ROWS x SEGS*8] bf16 tile, swizzled
template <int ROWS, int SEGS>
__device__ __forceinline__ void ld_sw(bf16* dst, const bf16* __restrict__ src,
                                      size_t row0, int ld, int k0, int tid) {
#pragma unroll
    for (int i = tid; i < ROWS * SEGS; i += 256) {
        int r = i / SEGS, c = i % SEGS;
        cp16(dst + r * SEGS * 8 + ((c ^ (r & 7)) << 3),
             src + (row0 + (size_t)r) * (size_t)ld + k0 + c * 8);
    }
}

__device__ __forceinline__ void group_barrier(int g, int tid) {
    __syncthreads();
    if (tid == 0) {
        volatile unsigned* vg = &g_ggen[g * 32];
        unsigned* cnt = &g_gcnt[g * 32];
        unsigned gen = *vg;
        __threadfence();
        unsigned old = atomicAdd(cnt, 1u);
        if (old == 15u) {
            atomicExch(cnt, 0u);
            __threadfence();
            *vg = gen + 1;
        } else {
            while (*vg == gen) {}
        }
        __threadfence();
    }
    __syncthreads();
}

// ---------------- prep kernels ----------------------------------------------
__global__ void split_kernel(const float* __restrict__ x, bf16* __restrict__ h,
                             bf16* __restrict__ l, size_t n) {
    size_t i = (size_t)blockIdx.x * 256 + threadIdx.x;
    if (i < n) {
        float v = x[i];
        bf16 a = __float2bfloat16(v);
        h[i] = a;
        l[i] = __float2bfloat16(v - __bfloat162float(a));
    }
}
__global__ void transpose_split(const float* __restrict__ W, bf16* __restrict__ Th,
                                bf16* __restrict__ Tl, int K, int N) {
    int idx = blockIdx.x * 256 + threadIdx.x;
    if (idx < N * K) {
        int n = idx / K, k = idx % K;
        float v = W[k * N + n];
        bf16 a = __float2bfloat16(v);
        Th[idx] = a;
        Tl[idx] = __float2bfloat16(v - __bfloat162float(a));
    }
}

// ---------------- phase-1 GEMM: out = act(A @ W^T + bias) -------------------
#define P1_AH 0
#define P1_AL 8192
#define P1_BH 16384
#define P1_BL 24576
#define P1_BUF 32768
#define P1_SMEM (2 * P1_BUF * 2)

__global__ __launch_bounds__(256) void ff_mma(
    const bf16* __restrict__ Ah, const bf16* __restrict__ Al,
    const bf16* __restrict__ Bh, const bf16* __restrict__ Bl,
    const float* __restrict__ bias, float* __restrict__ outF,
    bf16* __restrict__ outH, bf16* __restrict__ outL,
    int K, int N, int relu_split)
{
    extern __shared__ bf16 sm[];
    bf16* buf[2] = {sm, sm + P1_BUF};
    const int tid = threadIdx.x, lane = tid & 31, wid = tid >> 5;
    const int wm = wid & 3, wn = wid >> 2;
    const size_t rowBase = (size_t)blockIdx.y * 128;
    const int colBase = blockIdx.x * 128;
    const int nch = K / 64;

    float acc[2][8][4];
#pragma unroll
    for (int i = 0; i < 2; i++)
#pragma unroll
        for (int j = 0; j < 8; j++)
#pragma unroll
            for (int q = 0; q < 4; q++) acc[i][j][q] = 0.f;

    ld_sw<128, 8>(buf[0] + P1_AH, Ah, rowBase, K, 0, tid);
    ld_sw<128, 8>(buf[0] + P1_AL, Al, rowBase, K, 0, tid);
    ld_sw<128, 8>(buf[0] + P1_BH, Bh, (size_t)colBase, K, 0, tid);
    ld_sw<128, 8>(buf[0] + P1_BL, Bl, (size_t)colBase, K, 0, tid);
    CP_COMMIT();

    for (int kc = 0; kc < nch; kc++) {
        if (kc < nch - 1) {
            bf16* nb = buf[(kc + 1) & 1];
            int k0 = (kc + 1) * 64;
            ld_sw<128, 8>(nb + P1_AH, Ah, rowBase, K, k0, tid);
            ld_sw<128, 8>(nb + P1_AL, Al, rowBase, K, k0, tid);
            ld_sw<128, 8>(nb + P1_BH, Bh, (size_t)colBase, K, k0, tid);
            ld_sw<128, 8>(nb + P1_BL, Bl, (size_t)colBase, K, k0, tid);
            CP_COMMIT();
            CP_WAIT(1);
        } else {
            CP_WAIT(0);
        }
        __syncthreads();
        bf16* cb = buf[kc & 1];
#pragma unroll
        for (int ks = 0; ks < 4; ks++) {
            int ko = ks * 16;
            uint32_t ah[2][4], al[2][4];
#pragma unroll
            for (int mf = 0; mf < 2; mf++) {
                ldsm4_s(ah[mf], cb + P1_AH, 64, wm * 32 + mf * 16, ko, lane);
                ldsm4_s(al[mf], cb + P1_AL, 64, wm * 32 + mf * 16, ko, lane);
            }
#pragma unroll
            for (int nf = 0; nf < 8; nf++) {
                uint32_t bh[2], bl[2];
                ldsm2_s(bh, cb + P1_BH, 64, wn * 64 + nf * 8, ko, lane);
                ldsm2_s(bl, cb + P1_BL, 64, wn * 64 + nf * 8, ko, lane);
#pragma unroll
                for (int mf = 0; mf < 2; mf++) {
                    hmma(acc[mf][nf], ah[mf], bh);
                    hmma(acc[mf][nf], ah[mf], bl);
                    hmma(acc[mf][nf], al[mf], bh);
                }
            }
        }
        __syncthreads();
    }

#pragma unroll
    for (int mf = 0; mf < 2; mf++) {
#pragma unroll
        for (int nf = 0; nf < 8; nf++) {
            int cg = colBase + wn * 64 + nf * 8 + (lane & 3) * 2;
            float b0 = bias[cg], b1 = bias[cg + 1];
#pragma unroll
            for (int half = 0; half < 2; half++) {
                size_t rg = rowBase + wm * 32 + mf * 16 + (lane >> 2) + half * 8;
                float v0 = acc[mf][nf][half * 2] + b0;
                float v1 = acc[mf][nf][half * 2 + 1] + b1;
                if (relu_split) {
                    v0 = fmaxf(v0, 0.f);
                    v1 = fmaxf(v1, 0.f);
                    __nv_bfloat162 hv, lv;
                    hv.x = __float2bfloat16(v0);
                    hv.y = __float2bfloat16(v1);
                    lv.x = __float2bfloat16(v0 - __bfloat162float(hv.x));
                    lv.y = __float2bfloat16(v1 - __bfloat162float(hv.y));
                    *(__nv_bfloat162*)&outH[rg * N + cg] = hv;
                    *(__nv_bfloat162*)&outL[rg * N + cg] = lv;
                } else {
                    *(float2*)&outF[rg * N + cg] = make_float2(v0, v1);
                }
            }
        }
    }
}

// ---------------- persistent recurrence: 8 groups x 16 CTAs -----------------
// SMEM: w1h slice resident (128 KB) + 96 KB dynamic region.
// Phase A: 4-stage h pipeline (16 KB/stage) aliased into dynamic region.
// Phase B: 2 stages x (inter 16 KB + w2h 32 KB); W prefetched pre-barrier.
#define RW_H 0
#define RW_L 32768
#define RD 65536
#define PB_AH 0
#define PB_AL 4096
#define PB_WH 8192
#define PB_WL 16384
#define PB_STAGE 24576
#define PA_STAGE 8192
#define R_SMEM ((65536 + 2 * 24576) * 2)

__global__ __launch_bounds__(256) void recurrence(
    const float* __restrict__ b1h, const float* __restrict__ b2h,
    const int* __restrict__ lens, float* __restrict__ out)
{
    extern __shared__ bf16 sm[];
    bf16* smWH = sm + RW_H;
    bf16* smWL = sm + RW_L;
    const int tid = threadIdx.x, lane = tid & 31, wid = tid >> 5;
    const int wm = wid & 1, wn = wid >> 1;  // 2m x 4n warps
    const int cta = blockIdx.x;
    const int grp = cta >> 4;
    const size_t rbase = (size_t)grp * 32;
    const int cbaseA = (cta & 15) * 32;
    const int cbaseB = (cta & 15) * 64;

    // zero split h state (replayed graph)
    for (int i = tid; i < 2048; i += 256) {
        int j = (int)rbase * H_ + (cta & 15) * 2048 + i;
        g_hh[j] = __float2bfloat16(0.f);
        g_hl[j] = __float2bfloat16(0.f);
    }
    __threadfence();

    // resident phase-A weights (once)
    for (int i = tid; i < 32 * 128; i += 256) {
        int r = i >> 7, c = i & 127;
        int d = r * 1024 + ((c ^ (r & 7)) << 3);
        *(uint4*)(smWH + d) = *(const uint4*)&g_w1hTh[(size_t)(cbaseA + r) * H_ + c * 8];
        *(uint4*)(smWL + d) = *(const uint4*)&g_w1hTl[(size_t)(cbaseA + r) * H_ + c * 8];
    }
    group_barrier(grp, tid);

    const size_t rg0 = rbase + wm * 16 + (lane >> 2);
    const size_t rg1 = rg0 + 8;
    const int len0 = lens[rg0], len1 = lens[rg1];
    const int cgA = cbaseA + wn * 8 + (lane & 3) * 2;
    const float pb1_0 = b1h[cgA], pb1_1 = b1h[cgA + 1];
    float pb2[2][2];
#pragma unroll
    for (int nf = 0; nf < 2; nf++) {
        int cg = cbaseB + wn * 16 + nf * 8 + (lane & 3) * 2;
        pb2[nf][0] = b2h[cg];
        pb2[nf][1] = b2h[cg + 1];
    }
    float h_prev[2][4];
#pragma unroll
    for (int nf = 0; nf < 2; nf++)
#pragma unroll
        for (int q = 0; q < 4; q++) h_prev[nf][q] = 0.f;

    for (int t = 0; t < S_; t++) {
        // ---- issue phase-A h chunks 0..3 (4-stage pipeline) ----
#pragma unroll
        for (int p = 0; p < 4; p++) {
            bf16* hs = sm + RD + p * PA_STAGE;
            ld_sw<32, 16>(hs, g_hh, rbase, H_, p * 128, tid);
            ld_sw<32, 16>(hs + 4096, g_hl, rbase, H_, p * 128, tid);
            CP_COMMIT();
        }

        // ================= phase A =================
        float accA[3][4];
#pragma unroll
        for (int i = 0; i < 3; i++)
#pragma unroll
            for (int q = 0; q < 4; q++) accA[i][q] = 0.f;

#pragma unroll
        for (int kc = 0; kc < 8; kc++) {
            if (kc <= 4) { CP_WAIT(3); }
            else if (kc == 5) { CP_WAIT(2); }
            else if (kc == 6) { CP_WAIT(1); }
            else { CP_WAIT(0); }
            __syncthreads();
            bf16* hs = sm + RD + (kc & 3) * PA_STAGE;
#pragma unroll
            for (int ks = 0; ks < 8; ks++) {
                int ko = ks * 16;
                uint32_t ah[4], al[4], bh[2], bl[2];
                ldsm4_s(ah, hs, 128, wm * 16, ko, lane);
                ldsm4_s(al, hs + 4096, 128, wm * 16, ko, lane);
                ldsm2_s(bh, smWH, 1024, wn * 8, kc * 128 + ko, lane);
                ldsm2_s(bl, smWL, 1024, wn * 8, kc * 128 + ko, lane);
                hmma(accA[0], ah, bh);
                hmma(accA[1], ah, bl);
                hmma(accA[2], al, bh);
            }
            __syncthreads();
            if (kc < 4) {
                bf16* ns = sm + RD + (kc & 3) * PA_STAGE;
                ld_sw<32, 16>(ns, g_hh, rbase, H_, (kc + 4) * 128, tid);
                ld_sw<32, 16>(ns + 4096, g_hl, rbase, H_, (kc + 4) * 128, tid);
                CP_COMMIT();
            }
        }

        // ---- barrier-independent prefetch: W2 chunks 0,1 + xh registers ----
        ld_sw<64, 16>(sm + RD + PB_WH, g_w2hTh, (size_t)cbaseB, HH_, 0, tid);
        ld_sw<64, 16>(sm + RD + PB_WL, g_w2hTl, (size_t)cbaseB, HH_, 0, tid);
        CP_COMMIT();
        ld_sw<64, 16>(sm + RD + PB_STAGE + PB_WH, g_w2hTh, (size_t)cbaseB, HH_, 128, tid);
        ld_sw<64, 16>(sm + RD + PB_STAGE + PB_WL, g_w2hTl, (size_t)cbaseB, HH_, 128, tid);
        CP_COMMIT();
        float2 xv[2][2];
#pragma unroll
        for (int nf = 0; nf < 2; nf++) {
            int cg = cbaseB + wn * 16 + nf * 8 + (lane & 3) * 2;
            xv[nf][0] = *(const float2*)&g_xh[(rg0 * S_ + t) * H_ + cg];
            xv[nf][1] = *(const float2*)&g_xh[(rg1 * S_ + t) * H_ + cg];
        }

        // ---- epilogue A: relu + split -> g_ih/g_il ----
        {
#pragma unroll
            for (int half = 0; half < 2; half++) {
                size_t rg = (half == 0) ? rg0 : rg1;
                float v0 = fmaxf(accA[0][half * 2] + accA[1][half * 2] +
                                 accA[2][half * 2] + pb1_0, 0.f);
                float v1 = fmaxf(accA[0][half * 2 + 1] + accA[1][half * 2 + 1] +
                                 accA[2][half * 2 + 1] + pb1_1, 0.f);
                __nv_bfloat162 hv, lv;
                hv.x = __float2bfloat16(v0);
                hv.y = __float2bfloat16(v1);
                lv.x = __float2bfloat16(v0 - __bfloat162float(hv.x));
                lv.y = __float2bfloat16(v1 - __bfloat162float(hv.y));
                *(__nv_bfloat162*)&g_ih[rg * HH_ + cgA] = hv;
                *(__nv_bfloat162*)&g_il[rg * HH_ + cgA] = lv;
            }
        }
        __threadfence();
        group_barrier(grp, tid);

        // ---- post-barrier: inter chunks 0,1 ----
        ld_sw<32, 16>(sm + RD + PB_AH, g_ih, rbase, HH_, 0, tid);
        ld_sw<32, 16>(sm + RD + PB_AL, g_il, rbase, HH_, 0, tid);
        CP_COMMIT();
        ld_sw<32, 16>(sm + RD + PB_STAGE + PB_AH, g_ih, rbase, HH_, 128, tid);
        ld_sw<32, 16>(sm + RD + PB_STAGE + PB_AL, g_il, rbase, HH_, 128, tid);
        CP_COMMIT();

        // ================= phase B =================
        float accB[2][3][4];
#pragma unroll
        for (int nf = 0; nf < 2; nf++)
#pragma unroll
            for (int i = 0; i < 3; i++)
#pragma unroll
                for (int q = 0; q < 4; q++) accB[nf][i][q] = 0.f;

#pragma unroll
        for (int kc = 0; kc < 4; kc++) {
            if (kc < 3) { CP_WAIT(1); } else { CP_WAIT(0); }
            __syncthreads();
            bf16* cb = sm + RD + (kc & 1) * PB_STAGE;
#pragma unroll
            for (int ks = 0; ks < 8; ks++) {
                int ko = ks * 16;
                uint32_t ah[4], al[4];
                ldsm4_s(ah, cb + PB_AH, 128, wm * 16, ko, lane);
                ldsm4_s(al, cb + PB_AL, 128, wm * 16, ko, lane);
#pragma unroll
                for (int nf = 0; nf < 2; nf++) {
                    uint32_t bh[2], bl[2];
                    ldsm2_s(bh, cb + PB_WH, 128, wn * 16 + nf * 8, ko, lane);
                    ldsm2_s(bl, cb + PB_WL, 128, wn * 16 + nf * 8, ko, lane);
                    hmma(accB[nf][0], ah, bh);
                    hmma(accB[nf][1], ah, bl);
                    hmma(accB[nf][2], al, bh);
                }
            }
            __syncthreads();
            if (kc < 2) {
                bf16* ns = sm + RD + (kc & 1) * PB_STAGE;
                int k0 = (kc + 2) * 128;
                ld_sw<32, 16>(ns + PB_AH, g_ih, rbase, HH_, k0, tid);
                ld_sw<32, 16>(ns + PB_AL, g_il, rbase, HH_, k0, tid);
                ld_sw<64, 16>(ns + PB_WH, g_w2hTh, (size_t)cbaseB, HH_, k0, tid);
                ld_sw<64, 16>(ns + PB_WL, g_w2hTl, (size_t)cbaseB, HH_, k0, tid);
                CP_COMMIT();
            }
        }

        // ---- epilogue B ----
#pragma unroll
        for (int nf = 0; nf < 2; nf++) {
            int cg = cbaseB + wn * 16 + nf * 8 + (lane & 3) * 2;
#pragma unroll
            for (int half = 0; half < 2; half++) {
                size_t rg = (half == 0) ? rg0 : rg1;
                bool on = t < ((half == 0) ? len0 : len1);
                float v0, v1;
                if (on) {
                    float s0 = accB[nf][0][half * 2] + accB[nf][1][half * 2] +
                               accB[nf][2][half * 2];
                    float s1 = accB[nf][0][half * 2 + 1] + accB[nf][1][half * 2 + 1] +
                               accB[nf][2][half * 2 + 1];
                    v0 = fast_tanh(xv[nf][half].x + s0 + pb2[nf][0]);
                    v1 = fast_tanh(xv[nf][half].y + s1 + pb2[nf][1]);
                    h_prev[nf][half * 2] = v0;
                    h_prev[nf][half * 2 + 1] = v1;
                    __nv_bfloat162 hv, lv;
                    hv.x = __float2bfloat16(v0);
                    hv.y = __float2bfloat16(v1);
                    lv.x = __float2bfloat16(v0 - __bfloat162float(hv.x));
                    lv.y = __float2bfloat16(v1 - __bfloat162float(hv.y));
                    *(__nv_bfloat162*)&g_hh[rg * H_ + cg] = hv;
                    *(__nv_bfloat162*)&g_hl[rg * H_ + cg] = lv;
                } else {
                    v0 = h_prev[nf][half * 2];
                    v1 = h_prev[nf][half * 2 + 1];
                }
                *(float2*)&out[(rg * S_ + t) * H_ + cg] = make_float2(v0, v1);
            }
        }
        __threadfence();
        group_barrier(grp, tid);
    }
}

// ---------------- launcher --------------------------------------------------
extern "C" void kernel_launch(void* const* d_in, const int* in_sizes, int n_in,
                              void* d_out, int out_size) {
    const float* seq = (const float*)d_in[0];
    const int* lens  = (const int*)d_in[1];
    const float* w1x = (const float*)d_in[2];
    const float* b1x = (const float*)d_in[3];
    const float* w2x = (const float*)d_in[4];
    const float* b2x = (const float*)d_in[5];
    const float* w1h = (const float*)d_in[6];
    const float* b1h = (const float*)d_in[7];
    const float* w2h = (const float*)d_in[8];
    const float* b2h = (const float*)d_in[9];
    float* out = (float*)d_out;

    bf16 *seqh, *seql, *tmph, *tmpl;
    bf16 *w1xh, *w1xl, *w2xh, *w2xl, *w1hh, *w1hl, *w2hh, *w2hl;
    float* xh;
    cudaGetSymbolAddress((void**)&seqh, g_seqh);
    cudaGetSymbolAddress((void**)&seql, g_seql);
    cudaGetSymbolAddress((void**)&tmph, g_tmph);
    cudaGetSymbolAddress((void**)&tmpl, g_tmpl);
    cudaGetSymbolAddress((void**)&xh, g_xh);
    cudaGetSymbolAddress((void**)&w1xh, g_w1xTh);
    cudaGetSymbolAddress((void**)&w1xl, g_w1xTl);
    cudaGetSymbolAddress((void**)&w2xh, g_w2xTh);
    cudaGetSymbolAddress((void**)&w2xl, g_w2xTl);
    cudaGetSymbolAddress((void**)&w1hh, g_w1hTh);
    cudaGetSymbolAddress((void**)&w1hl, g_w1hTl);
    cudaGetSymbolAddress((void**)&w2hh, g_w2hTh);
    cudaGetSymbolAddress((void**)&w2hl, g_w2hTl);

    cudaFuncSetAttribute(ff_mma, cudaFuncAttributeMaxDynamicSharedMemorySize, P1_SMEM);
    cudaFuncSetAttribute(recurrence, cudaFuncAttributeMaxDynamicSharedMemorySize, R_SMEM);

    size_t nseq = (size_t)MTOK * E_;
    split_kernel<<<(unsigned)((nseq + 255) / 256), 256>>>(seq, seqh, seql, nseq);
    transpose_split<<<(E_ * HH_ + 255) / 256, 256>>>(w1x, w1xh, w1xl, E_, HH_);
    transpose_split<<<(HH_ * H_ + 255) / 256, 256>>>(w2x, w2xh, w2xl, HH_, H_);
    transpose_split<<<(H_ * HH_ + 255) / 256, 256>>>(w1h, w1hh, w1hl, H_, HH_);
    transpose_split<<<(HH_ * H_ + 255) / 256, 256>>>(w2h, w2hh, w2hl, HH_, H_);

    ff_mma<<<dim3(HH_ / 128, MTOK / 128), 256, P1_SMEM>>>(
        seqh, seql, w1xh, w1xl, b1x, nullptr, tmph, tmpl, E_, HH_, 1);
    ff_mma<<<dim3(H_ / 128, MTOK / 128), 256, P1_SMEM>>>(
        tmph, tmpl, w2xh, w2xl, b2x, xh, nullptr, nullptr, HH_, H_, 0);

    recurrence<<<128, 256, R_SMEM>>>(b1h, b2h, lens, out);
}